// round 4
// baseline (speedup 1.0000x reference)
#include <cuda_runtime.h>
#include <cstdint>
#include <cstdio>

#define B_  128
#define S_  50
#define T_  32
#define TQ_ 32
#define H_  256
#define V_  50257
#define G3  768

typedef unsigned long long ull;

// ---------------- scratch (device globals; no allocation) ----------------
__device__ float g_ctx [B_*S_*H_];
__device__ float g_qemb[B_*TQ_*H_];
__device__ float g_gif [B_*S_*G3];
__device__ float g_gib [B_*S_*G3];
__device__ float g_giq [B_*TQ_*G3];
__device__ float g_outf[B_*S_*H_];
__device__ float g_outb[B_*S_*H_];
__device__ float g_q   [B_*H_];
__device__ float g_af  [B_*H_];

// ---------------- helpers ----------------
__device__ __forceinline__ float sigmoidf_(float x){ return 1.0f/(1.0f+expf(-x)); }

__device__ __forceinline__ ull pack2_(float lo, float hi){
    ull r; asm("mov.b64 %0, {%1, %2};" : "=l"(r) : "f"(lo), "f"(hi)); return r;
}
__device__ __forceinline__ ull dup2_(float v){
    ull r; asm("mov.b64 %0, {%1, %1};" : "=l"(r) : "f"(v)); return r;
}
__device__ __forceinline__ void fma2_(ull& d, ull a, ull b){
    asm("fma.rn.f32x2 %0, %1, %2, %0;" : "+l"(d) : "l"(a), "l"(b));
}
__device__ __forceinline__ void add2_(ull& d, ull o){
    asm("add.rn.f32x2 %0, %0, %1;" : "+l"(d) : "l"(o));
}
__device__ __forceinline__ float2 unpack2_(ull v){
    float2 r; asm("mov.b64 {%0, %1}, %2;" : "=f"(r.x), "=f"(r.y) : "l"(v)); return r;
}
__device__ __forceinline__ unsigned smem_u32_(const void* p){
    unsigned r;
    asm("{ .reg .u64 t; cvta.to.shared.u64 t, %1; cvt.u32.u64 %0, t; }" : "=r"(r) : "l"(p));
    return r;
}
__device__ __forceinline__ unsigned mapa_(unsigned laddr, unsigned rank){
    unsigned r;
    asm("mapa.shared::cluster.u32 %0, %1, %2;" : "=r"(r) : "r"(laddr), "r"(rank));
    return r;
}
__device__ __forceinline__ void st_cluster_f32_(unsigned addr, float a){
    asm volatile("st.shared::cluster.f32 [%0], %1;" :: "r"(addr), "f"(a) : "memory");
}
__device__ __forceinline__ void cluster_arrive_(){
    asm volatile("barrier.cluster.arrive.aligned;" ::: "memory");
}
__device__ __forceinline__ void cluster_wait_(){
    asm volatile("barrier.cluster.wait.aligned;" ::: "memory");
}
__device__ __forceinline__ unsigned ctarank_(){
    unsigned r; asm("mov.u32 %0, %%cluster_ctarank;" : "=r"(r)); return r;
}

// ---------------- 1) embedding + position encoding ----------------
__global__ void embed_pe_kernel(const int* __restrict__ ctx, const float* __restrict__ emb){
    int bs = blockIdx.x;          // b*S_ + s
    int h  = threadIdx.x;         // 0..255
    __shared__ int ids[T_];
    if (h < T_) ids[h] = ctx[bs*T_ + h];
    __syncthreads();
    float e = (float)h * (1.0f/255.0f);
    float acc = 0.f;
#pragma unroll
    for (int t = 0; t < T_; t++){
        float s = (float)t * (1.0f/31.0f);
        float l = 1.0f - s - e*(1.0f - 2.0f*s);
        acc += emb[(size_t)ids[t]*H_ + h] * l;
    }
    g_ctx[(size_t)bs*H_ + h] = acc;
}

__global__ void qemb_kernel(const int* __restrict__ q, const float* __restrict__ emb){
    int i = blockIdx.x;           // b*TQ_ + t
    int h = threadIdx.x;
    g_qemb[(size_t)i*H_ + h] = emb[(size_t)q[i]*H_ + h];
}

// ---------------- 2) GEMM core with packed f32x2 FMAs ----------------
// C[m,n] = sum_k A[m,k] * W[n,k] + bias[n]; K = 256. Tile 128(m) x 64(n).
__device__ __forceinline__ void gemm_body(const float* __restrict__ A,
                                          const float* __restrict__ W,
                                          const float* __restrict__ bias,
                                          float* __restrict__ C,
                                          int N, int bm, int bn)
{
    __shared__ float As[32][132];
    __shared__ float Bs[32][68];
    int tid = threadIdx.x;
    int tx = tid & 15, ty = tid >> 4;

    ull acc[4][4];
#pragma unroll
    for (int i = 0; i < 4; i++)
#pragma unroll
        for (int j = 0; j < 4; j++) acc[i][j] = 0ull;

    for (int k0 = 0; k0 < 256; k0 += 32){
#pragma unroll
        for (int i = 0; i < 4; i++){
            int lin = tid + i*256;
            int row = lin >> 3, kk = (lin & 7) << 2;
            float4 v = *(const float4*)(A + (size_t)(bm+row)*256 + k0 + kk);
            As[kk  ][row] = v.x; As[kk+1][row] = v.y;
            As[kk+2][row] = v.z; As[kk+3][row] = v.w;
        }
#pragma unroll
        for (int i = 0; i < 2; i++){
            int lin = tid + i*256;
            int row = lin >> 3, kk = (lin & 7) << 2;
            int n = bn + row;
            float4 v = make_float4(0.f,0.f,0.f,0.f);
            if (n < N) v = *(const float4*)(W + (size_t)n*256 + k0 + kk);
            Bs[kk  ][row] = v.x; Bs[kk+1][row] = v.y;
            Bs[kk+2][row] = v.z; Bs[kk+3][row] = v.w;
        }
        __syncthreads();
#pragma unroll
        for (int k = 0; k < 32; k++){
            float4 a0 = *(const float4*)(&As[k][ty*8]);
            float4 a1 = *(const float4*)(&As[k][ty*8+4]);
            float4 bv = *(const float4*)(&Bs[k][tx*4]);
            ull ap0 = pack2_(a0.x, a0.y);
            ull ap1 = pack2_(a0.z, a0.w);
            ull ap2 = pack2_(a1.x, a1.y);
            ull ap3 = pack2_(a1.z, a1.w);
            ull bd0 = dup2_(bv.x), bd1 = dup2_(bv.y), bd2 = dup2_(bv.z), bd3 = dup2_(bv.w);
            fma2_(acc[0][0], ap0, bd0); fma2_(acc[0][1], ap0, bd1);
            fma2_(acc[0][2], ap0, bd2); fma2_(acc[0][3], ap0, bd3);
            fma2_(acc[1][0], ap1, bd0); fma2_(acc[1][1], ap1, bd1);
            fma2_(acc[1][2], ap1, bd2); fma2_(acc[1][3], ap1, bd3);
            fma2_(acc[2][0], ap2, bd0); fma2_(acc[2][1], ap2, bd1);
            fma2_(acc[2][2], ap2, bd2); fma2_(acc[2][3], ap2, bd3);
            fma2_(acc[3][0], ap3, bd0); fma2_(acc[3][1], ap3, bd1);
            fma2_(acc[3][2], ap3, bd2); fma2_(acc[3][3], ap3, bd3);
        }
        __syncthreads();
    }
#pragma unroll
    for (int ip = 0; ip < 4; ip++){
        int m = bm + ty*8 + ip*2;
#pragma unroll
        for (int j = 0; j < 4; j++){
            int n = bn + tx*4 + j;
            if (n < N){
                float2 v = unpack2_(acc[ip][j]);
                float bb = bias[n];
                C[(size_t)m*N + n]       = v.x + bb;
                C[(size_t)(m+1)*N + n]   = v.y + bb;
            }
        }
    }
}

// Fused kernel for the three input-gate GEMMs (z selects the problem)
__global__ __launch_bounds__(256) void gemm3_kernel(
    const float* A0, const float* W0, const float* c0, float* C0, int M0,
    const float* A1, const float* W1, const float* c1, float* C1, int M1,
    const float* A2, const float* W2, const float* c2, float* C2, int M2)
{
    const float *A, *W, *cb; float* C; int M;
    if (blockIdx.z == 0){ A=A0; W=W0; cb=c0; C=C0; M=M0; }
    else if (blockIdx.z == 1){ A=A1; W=W1; cb=c1; C=C1; M=M1; }
    else { A=A2; W=W2; cb=c2; C=C2; M=M2; }
    int bm = blockIdx.x * 128;
    if (bm >= M) return;
    gemm_body(A, W, cb, C, G3, bm, blockIdx.y * 64);
}

__global__ __launch_bounds__(256) void gemm_atb(const float* __restrict__ A,
                                                const float* __restrict__ W,
                                                const float* __restrict__ bias,
                                                float* __restrict__ C, int N)
{
    gemm_body(A, W, bias, C, N, blockIdx.x * 128, blockIdx.y * 64);
}

// ---------------- 3) GRU recurrences ----------------
// Cluster of 4 CTAs; CTA owns 64 hidden j (192 Whh rows, k-major in smem).
// 24 clusters: chains f(0..7), b(8..15), q(16..23); 16 batches per cluster.
// 512 threads/CTA (16 warps = 4/SMSP for latency hiding).
// Thread = (jp: 32 j-pairs, bg: 4 batch groups, ks: 4 k-slices of 64).
//   tid = jp*16 + bg*4 + ks  -> warp = 2 jp x 4 bg x 4 ks
// Per k: 3 broadcast LDS.64 (w j-pairs), 1 broadcast LDS.128 (h 4 batches),
//        4 dup, 12 FFMA2. k-partials combined with 2-round butterfly shfl.
#define GRU_CL_B   16
#define GRU_WT_ST  194
#define GRU_SMEM_FLOATS (256*GRU_WT_ST + 2*256*GRU_CL_B)
#define GRU_SMEM_BYTES  (GRU_SMEM_FLOATS*4)

__global__ void __cluster_dims__(4,1,1) __launch_bounds__(512,1)
gru_kernel(const float* __restrict__ Whh_f, const float* __restrict__ Whh_b, const float* __restrict__ Whh_q,
           const float* __restrict__ bhh_f, const float* __restrict__ bhh_b, const float* __restrict__ bhh_q)
{
    extern __shared__ float sm[];
    float* Wt   = sm;                       // [256 k][194]  (cols: g*64 + j)
    float* hbuf = sm + 256*GRU_WT_ST;       // [2][256 j][16 b]

    int tid = threadIdx.x;
    unsigned rank = ctarank_();
    int cid   = blockIdx.x >> 2;
    int chain = cid >> 3;                   // 0=f, 1=b, 2=q
    int b0    = (cid & 7) * GRU_CL_B;

    const float *Whh, *bhh, *gi;
    float* outp;
    int steps;
    if (chain == 0){ Whh = Whh_f; bhh = bhh_f; gi = g_gif; outp = g_outf; steps = S_;  }
    else if (chain == 1){ Whh = Whh_b; bhh = bhh_b; gi = g_gib; outp = g_outb; steps = S_;  }
    else { Whh = Whh_q; bhh = bhh_q; gi = g_giq; outp = g_q;    steps = TQ_; }

    // load Whh slice transposed: Wt[k][g*64+jj] = Whh[g*256 + rank*64 + jj][k]
    {
        int kk = tid & 255;
        int half = tid >> 8;                // 0: rows 0..95, 1: rows 96..191
#pragma unroll 4
        for (int rr = half*96; rr < half*96 + 96; rr++){
            int g = rr >> 6, jj = rr & 63;
            Wt[kk*GRU_WT_ST + rr] = Whh[((size_t)(g*256 + (int)rank*64 + jj))*256 + kk];
        }
        for (int i = tid; i < 2*256*GRU_CL_B; i += 512) hbuf[i] = 0.f;
    }

    int ks = tid & 3;                       // k-slice (64 k each)
    int bg = (tid >> 2) & 3;                // batch group (4 batches)
    int jp = tid >> 4;                      // 0..31 j-pair
    int j0 = jp*2;
    int jglob0 = (int)rank*64 + j0;

    // peer hbuf base addresses (mapa hoisted out of the loop)
    unsigned hb_l = smem_u32_(hbuf);
    unsigned peer0 = mapa_(hb_l, 0), peer1 = mapa_(hb_l, 1);
    unsigned peer2 = mapa_(hb_l, 2), peer3 = mapa_(hb_l, 3);

    float2 br2 = *(const float2*)(bhh       + jglob0);
    float2 bz2 = *(const float2*)(bhh + 256 + jglob0);
    float2 bn2 = *(const float2*)(bhh + 512 + jglob0);

    int bb = b0 + bg*4 + ks;                // this thread's epilogue batch
    float hp0 = 0.f, hp1 = 0.f;             // h_prev for (bb, j0) and (bb, j0+1)

    const float* wbase = Wt + ks*64*GRU_WT_ST + j0;
    const float* hbase = hbuf + ks*64*GRU_CL_B + bg*4;

    cluster_arrive_();

    // prefetch gi for step 0 (this thread's batch)
    float2 gr0, gz0, gn0;
    {
        int pos = (chain == 1) ? (S_ - 1) : 0;
        const float* p0 = gi + ((size_t)bb*steps + pos)*G3 + jglob0;
        gr0 = *(const float2*)(p0); gz0 = *(const float2*)(p0+256); gn0 = *(const float2*)(p0+512);
    }
    cluster_wait_();

    for (int step = 0; step < steps; step++){
        int cur = step & 1, nxt = cur ^ 1;
        int pos = (chain == 1) ? (S_ - 1 - step) : step;

        // matvec over this thread's 64-k slice: 2 j x 4 batches x 3 gates
        ull aR[4] = {0,0,0,0}, aZ[4] = {0,0,0,0}, aN[4] = {0,0,0,0};
        const float* wp = wbase;
        const float* hq = hbase + cur*(256*GRU_CL_B);
#pragma unroll 4
        for (int k = 0; k < 64; k++){
            ull wr = *(const ull*)(wp);
            ull wz = *(const ull*)(wp + 64);
            ull wn = *(const ull*)(wp + 128);
            float4 h4 = *(const float4*)(hq);
            ull hd0 = dup2_(h4.x), hd1 = dup2_(h4.y), hd2 = dup2_(h4.z), hd3 = dup2_(h4.w);
            fma2_(aR[0], wr, hd0); fma2_(aR[1], wr, hd1); fma2_(aR[2], wr, hd2); fma2_(aR[3], wr, hd3);
            fma2_(aZ[0], wz, hd0); fma2_(aZ[1], wz, hd1); fma2_(aZ[2], wz, hd2); fma2_(aZ[3], wz, hd3);
            fma2_(aN[0], wn, hd0); fma2_(aN[1], wn, hd1); fma2_(aN[2], wn, hd2); fma2_(aN[3], wn, hd3);
            wp += GRU_WT_ST; hq += GRU_CL_B;
        }
        // combine the 4 k-slices (lanes differ in ks = bits 0-1): full butterfly
#pragma unroll
        for (int i = 0; i < 4; i++){
            add2_(aR[i], __shfl_xor_sync(0xffffffffu, aR[i], 1));
            add2_(aZ[i], __shfl_xor_sync(0xffffffffu, aZ[i], 1));
            add2_(aN[i], __shfl_xor_sync(0xffffffffu, aN[i], 1));
            add2_(aR[i], __shfl_xor_sync(0xffffffffu, aR[i], 2));
            add2_(aZ[i], __shfl_xor_sync(0xffffffffu, aZ[i], 2));
            add2_(aN[i], __shfl_xor_sync(0xffffffffu, aN[i], 2));
        }

        // epilogue: this thread finalizes batch bb (accumulator index = ks)
        float2 Ar = unpack2_(aR[ks]), Az = unpack2_(aZ[ks]), An = unpack2_(aN[ks]);

        float r0 = sigmoidf_(gr0.x + Ar.x + br2.x);
        float z0 = sigmoidf_(gz0.x + Az.x + bz2.x);
        float n0 = tanhf   (gn0.x + r0*(An.x + bn2.x));
        float h0 = (1.f - z0)*n0 + z0*hp0; hp0 = h0;
        float r1 = sigmoidf_(gr0.y + Ar.y + br2.y);
        float z1 = sigmoidf_(gz0.y + Az.y + bz2.y);
        float n1 = tanhf   (gn0.y + r1*(An.y + bn2.y));
        float h1 = (1.f - z1)*n1 + z1*hp1; hp1 = h1;

        // write outputs
        if (chain == 2){
            if (step == steps - 1)
                *(float2*)(outp + (size_t)bb*H_ + jglob0) = make_float2(h0, h1);
        } else {
            *(float2*)(outp + ((size_t)bb*S_ + pos)*H_ + jglob0) = make_float2(h0, h1);
        }

        // broadcast h (2 j x 1 batch) to all 4 CTAs' hbuf[nxt]
        {
            unsigned off0 = (unsigned)(((nxt*256 + jglob0  )*GRU_CL_B + (bg*4 + ks))*4);
            unsigned off1 = (unsigned)(((nxt*256 + jglob0+1)*GRU_CL_B + (bg*4 + ks))*4);
            st_cluster_f32_(peer0 + off0, h0); st_cluster_f32_(peer0 + off1, h1);
            st_cluster_f32_(peer1 + off0, h0); st_cluster_f32_(peer1 + off1, h1);
            st_cluster_f32_(peer2 + off0, h0); st_cluster_f32_(peer2 + off1, h1);
            st_cluster_f32_(peer3 + off0, h0); st_cluster_f32_(peer3 + off1, h1);
        }
        cluster_arrive_();

        // prefetch gi for next step (overlaps peer skew)
        if (step + 1 < steps){
            int np = (chain == 1) ? (S_ - 2 - step) : (step + 1);
            const float* p0 = gi + ((size_t)bb*steps + np)*G3 + jglob0;
            gr0 = *(const float2*)(p0); gz0 = *(const float2*)(p0+256); gn0 = *(const float2*)(p0+512);
        }
        cluster_wait_();
    }
}

// ---------------- 4) attention + read + tanh(q*read) ----------------
__global__ void attn_kernel(){
    int b = blockIdx.x, h = threadIdx.x;
    __shared__ float en[S_];
    __shared__ float red[8];
    float qh = g_q[(size_t)b*H_ + h];
    int lane = h & 31, wid = h >> 5;
    for (int s = 0; s < S_; s++){
        float f = g_outf[((size_t)b*S_ + s)*H_ + h] + g_outb[((size_t)b*S_ + s)*H_ + h];
        float p = f * qh;
#pragma unroll
        for (int o = 16; o; o >>= 1) p += __shfl_xor_sync(0xffffffffu, p, o);
        if (lane == 0) red[wid] = p;
        __syncthreads();
        if (h < 8){
            float t = red[h];
            t += __shfl_xor_sync(0xffu, t, 4);
            t += __shfl_xor_sync(0xffu, t, 2);
            t += __shfl_xor_sync(0xffu, t, 1);
            if (h == 0) en[s] = t;
        }
        __syncthreads();
    }
    float mx = -1e30f;
    for (int s = 0; s < S_; s++) mx = fmaxf(mx, en[s]);
    float sum = 0.f;
    for (int s = 0; s < S_; s++) sum += expf(en[s] - mx);
    float inv = 1.f / sum;
    float rd = 0.f;
    for (int s = 0; s < S_; s++){
        float a = expf(en[s] - mx) * inv;
        rd += a * (g_outf[((size_t)b*S_ + s)*H_ + h] + g_outb[((size_t)b*S_ + s)*H_ + h]);
    }
    g_af[(size_t)b*H_ + h] = tanhf(qh * rd);
}

// ---------------- launch ----------------
extern "C" void kernel_launch(void* const* d_in, const int* in_sizes, int n_in,
                              void* d_out, int out_size)
{
    const int*   contexts  = (const int*)  d_in[0];
    const int*   questions = (const int*)  d_in[1];
    const float* emb       = (const float*)d_in[2];
    const float* Wih_f     = (const float*)d_in[3];
    const float* Whh_f     = (const float*)d_in[4];
    const float* bih_f     = (const float*)d_in[5];
    const float* bhh_f     = (const float*)d_in[6];
    const float* Wih_b     = (const float*)d_in[7];
    const float* Whh_b     = (const float*)d_in[8];
    const float* bih_b     = (const float*)d_in[9];
    const float* bhh_b     = (const float*)d_in[10];
    const float* Wih_q     = (const float*)d_in[11];
    const float* Whh_q     = (const float*)d_in[12];
    const float* bih_q     = (const float*)d_in[13];
    const float* bhh_q     = (const float*)d_in[14];
    const float* Wo        = (const float*)d_in[15];
    const float* bo        = (const float*)d_in[16];
    float* out = (float*)d_out;

    float *p_ctx, *p_qemb, *p_gif, *p_gib, *p_giq, *p_af;
    cudaGetSymbolAddress((void**)&p_ctx,  g_ctx);
    cudaGetSymbolAddress((void**)&p_qemb, g_qemb);
    cudaGetSymbolAddress((void**)&p_gif,  g_gif);
    cudaGetSymbolAddress((void**)&p_gib,  g_gib);
    cudaGetSymbolAddress((void**)&p_giq,  g_giq);
    cudaGetSymbolAddress((void**)&p_af,   g_af);

    cudaFuncSetAttribute(gru_kernel, cudaFuncAttributeMaxDynamicSharedMemorySize, GRU_SMEM_BYTES);

    // 1) embeddings
    embed_pe_kernel<<<B_*S_, 256>>>(contexts, emb);
    qemb_kernel<<<B_*TQ_, 256>>>(questions, emb);

    // 2) all three input-gate GEMMs in one launch (z selects problem)
    gemm3_kernel<<<dim3(B_*S_/128, G3/64, 3), 256>>>(
        p_ctx,  Wih_f, bih_f, p_gif, B_*S_,
        p_ctx,  Wih_b, bih_b, p_gib, B_*S_,
        p_qemb, Wih_q, bih_q, p_giq, B_*TQ_);

    // 3) all three GRU chains concurrently (24 clusters x 4 CTAs)
    gru_kernel<<<96, 512, GRU_SMEM_BYTES>>>(Whh_f, Whh_b, Whh_q, bhh_f, bhh_b, bhh_q);

    // 4) attention + read + tanh
    attn_kernel<<<B_, 256>>>();

    // 5) vocab projection: out = af @ Wo^T + bo
    gemm_atb<<<dim3(1, (V_ + 63)/64), 256>>>(p_af, Wo, bo, out, V_);
}

// round 5
// speedup vs baseline: 1.7724x; 1.7724x over previous
#include <cuda_runtime.h>
#include <cstdint>
#include <cstdio>

#define B_  128
#define S_  50
#define T_  32
#define TQ_ 32
#define H_  256
#define V_  50257
#define G3  768

typedef unsigned long long ull;

// ---------------- scratch (device globals; no allocation) ----------------
__device__ float g_ctx [B_*S_*H_];
__device__ float g_qemb[B_*TQ_*H_];
__device__ float g_gif [B_*S_*G3];
__device__ float g_gib [B_*S_*G3];
__device__ float g_giq [B_*TQ_*G3];
__device__ float g_outf[B_*S_*H_];
__device__ float g_outb[B_*S_*H_];
__device__ float g_q   [B_*H_];
__device__ float g_af  [B_*H_];

// ---------------- helpers ----------------
__device__ __forceinline__ float sigmoidf_(float x){ return 1.0f/(1.0f+expf(-x)); }

__device__ __forceinline__ ull pack2_(float lo, float hi){
    ull r; asm("mov.b64 %0, {%1, %2};" : "=l"(r) : "f"(lo), "f"(hi)); return r;
}
__device__ __forceinline__ ull dup2_(float v){
    ull r; asm("mov.b64 %0, {%1, %1};" : "=l"(r) : "f"(v)); return r;
}
__device__ __forceinline__ void fma2_(ull& d, ull a, ull b){
    asm("fma.rn.f32x2 %0, %1, %2, %0;" : "+l"(d) : "l"(a), "l"(b));
}
__device__ __forceinline__ void add2_(ull& d, ull o){
    asm("add.rn.f32x2 %0, %0, %1;" : "+l"(d) : "l"(o));
}
__device__ __forceinline__ float2 unpack2_(ull v){
    float2 r; asm("mov.b64 {%0, %1}, %2;" : "=f"(r.x), "=f"(r.y) : "l"(v)); return r;
}
__device__ __forceinline__ unsigned smem_u32_(const void* p){
    unsigned r;
    asm("{ .reg .u64 t; cvta.to.shared.u64 t, %1; cvt.u32.u64 %0, t; }" : "=r"(r) : "l"(p));
    return r;
}
__device__ __forceinline__ unsigned mapa_(unsigned laddr, unsigned rank){
    unsigned r;
    asm("mapa.shared::cluster.u32 %0, %1, %2;" : "=r"(r) : "r"(laddr), "r"(rank));
    return r;
}
__device__ __forceinline__ void st_cluster_f32_(unsigned addr, float a){
    asm volatile("st.shared::cluster.f32 [%0], %1;" :: "r"(addr), "f"(a) : "memory");
}
__device__ __forceinline__ void cluster_arrive_(){
    asm volatile("barrier.cluster.arrive.aligned;" ::: "memory");
}
__device__ __forceinline__ void cluster_wait_(){
    asm volatile("barrier.cluster.wait.aligned;" ::: "memory");
}
__device__ __forceinline__ unsigned ctarank_(){
    unsigned r; asm("mov.u32 %0, %%cluster_ctarank;" : "=r"(r)); return r;
}

// ---------------- 1) embedding + position encoding ----------------
__global__ void embed_pe_kernel(const int* __restrict__ ctx, const float* __restrict__ emb){
    int bs = blockIdx.x;          // b*S_ + s
    int h  = threadIdx.x;         // 0..255
    __shared__ int ids[T_];
    if (h < T_) ids[h] = ctx[bs*T_ + h];
    __syncthreads();
    float e = (float)h * (1.0f/255.0f);
    float acc = 0.f;
#pragma unroll
    for (int t = 0; t < T_; t++){
        float s = (float)t * (1.0f/31.0f);
        float l = 1.0f - s - e*(1.0f - 2.0f*s);
        acc += emb[(size_t)ids[t]*H_ + h] * l;
    }
    g_ctx[(size_t)bs*H_ + h] = acc;
}

__global__ void qemb_kernel(const int* __restrict__ q, const float* __restrict__ emb){
    int i = blockIdx.x;           // b*TQ_ + t
    int h = threadIdx.x;
    g_qemb[(size_t)i*H_ + h] = emb[(size_t)q[i]*H_ + h];
}

// ---------------- 2) GEMM core with packed f32x2 FMAs ----------------
// C[m,n] = sum_k A[m,k] * W[n,k] + bias[n]; K = 256. Tile 128(m) x 64(n).
__device__ __forceinline__ void gemm_body(const float* __restrict__ A,
                                          const float* __restrict__ W,
                                          const float* __restrict__ bias,
                                          float* __restrict__ C,
                                          int N, int bm, int bn)
{
    __shared__ float As[32][132];
    __shared__ float Bs[32][68];
    int tid = threadIdx.x;
    int tx = tid & 15, ty = tid >> 4;

    ull acc[4][4];
#pragma unroll
    for (int i = 0; i < 4; i++)
#pragma unroll
        for (int j = 0; j < 4; j++) acc[i][j] = 0ull;

    for (int k0 = 0; k0 < 256; k0 += 32){
#pragma unroll
        for (int i = 0; i < 4; i++){
            int lin = tid + i*256;
            int row = lin >> 3, kk = (lin & 7) << 2;
            float4 v = *(const float4*)(A + (size_t)(bm+row)*256 + k0 + kk);
            As[kk  ][row] = v.x; As[kk+1][row] = v.y;
            As[kk+2][row] = v.z; As[kk+3][row] = v.w;
        }
#pragma unroll
        for (int i = 0; i < 2; i++){
            int lin = tid + i*256;
            int row = lin >> 3, kk = (lin & 7) << 2;
            int n = bn + row;
            float4 v = make_float4(0.f,0.f,0.f,0.f);
            if (n < N) v = *(const float4*)(W + (size_t)n*256 + k0 + kk);
            Bs[kk  ][row] = v.x; Bs[kk+1][row] = v.y;
            Bs[kk+2][row] = v.z; Bs[kk+3][row] = v.w;
        }
        __syncthreads();
#pragma unroll
        for (int k = 0; k < 32; k++){
            float4 a0 = *(const float4*)(&As[k][ty*8]);
            float4 a1 = *(const float4*)(&As[k][ty*8+4]);
            float4 bv = *(const float4*)(&Bs[k][tx*4]);
            ull ap0 = pack2_(a0.x, a0.y);
            ull ap1 = pack2_(a0.z, a0.w);
            ull ap2 = pack2_(a1.x, a1.y);
            ull ap3 = pack2_(a1.z, a1.w);
            ull bd0 = dup2_(bv.x), bd1 = dup2_(bv.y), bd2 = dup2_(bv.z), bd3 = dup2_(bv.w);
            fma2_(acc[0][0], ap0, bd0); fma2_(acc[0][1], ap0, bd1);
            fma2_(acc[0][2], ap0, bd2); fma2_(acc[0][3], ap0, bd3);
            fma2_(acc[1][0], ap1, bd0); fma2_(acc[1][1], ap1, bd1);
            fma2_(acc[1][2], ap1, bd2); fma2_(acc[1][3], ap1, bd3);
            fma2_(acc[2][0], ap2, bd0); fma2_(acc[2][1], ap2, bd1);
            fma2_(acc[2][2], ap2, bd2); fma2_(acc[2][3], ap2, bd3);
            fma2_(acc[3][0], ap3, bd0); fma2_(acc[3][1], ap3, bd1);
            fma2_(acc[3][2], ap3, bd2); fma2_(acc[3][3], ap3, bd3);
        }
        __syncthreads();
    }
#pragma unroll
    for (int ip = 0; ip < 4; ip++){
        int m = bm + ty*8 + ip*2;
#pragma unroll
        for (int j = 0; j < 4; j++){
            int n = bn + tx*4 + j;
            if (n < N){
                float2 v = unpack2_(acc[ip][j]);
                float bb = bias[n];
                C[(size_t)m*N + n]       = v.x + bb;
                C[(size_t)(m+1)*N + n]   = v.y + bb;
            }
        }
    }
}

// Fused kernel for the three input-gate GEMMs (z selects the problem)
__global__ __launch_bounds__(256) void gemm3_kernel(
    const float* A0, const float* W0, const float* c0, float* C0, int M0,
    const float* A1, const float* W1, const float* c1, float* C1, int M1,
    const float* A2, const float* W2, const float* c2, float* C2, int M2)
{
    const float *A, *W, *cb; float* C; int M;
    if (blockIdx.z == 0){ A=A0; W=W0; cb=c0; C=C0; M=M0; }
    else if (blockIdx.z == 1){ A=A1; W=W1; cb=c1; C=C1; M=M1; }
    else { A=A2; W=W2; cb=c2; C=C2; M=M2; }
    int bm = blockIdx.x * 128;
    if (bm >= M) return;
    gemm_body(A, W, cb, C, G3, bm, blockIdx.y * 64);
}

__global__ __launch_bounds__(256) void gemm_atb(const float* __restrict__ A,
                                                const float* __restrict__ W,
                                                const float* __restrict__ bias,
                                                float* __restrict__ C, int N)
{
    gemm_body(A, W, bias, C, N, blockIdx.x * 128, blockIdx.y * 64);
}

// ---------------- 3) GRU recurrences ----------------
// Cluster of 4 CTAs; CTA owns 64 hidden j (192 Whh rows, k-major in smem).
// 24 clusters: chains f(0..7), b(8..15), q(16..23); 16 batches per cluster.
// 512 threads/CTA (16 warps = 4/SMSP).
// Thread = (jp: 32 j-pairs, bg: 4 batch groups, ks: 4 k-slices of 64).
// BANK-SKEWED layout (the R4 fix):
//   Wt  : [ks][64 k][194], slice stride 64*194+8  -> ks bank offsets {0,8,16,24}
//   hbuf: [buf][ks][64 k][16 b], slice stride 64*16+16 -> ks bank offsets {0,16,0,16}
// Per k: 3 w LDS.64 (1 phase), 1 h LDS.128 (2 phases), 4 dup, 12 FFMA2.
#define GRU_CL_B   16
#define GRU_WT_ST  194
#define WSLICE     (64*GRU_WT_ST + 8)     // 12424 floats
#define HSLICE     (64*GRU_CL_B + 16)     // 1040 floats
#define HBUFSZ     (4*HSLICE)             // 4160 floats
#define GRU_SMEM_FLOATS (4*WSLICE + 2*HBUFSZ)
#define GRU_SMEM_BYTES  (GRU_SMEM_FLOATS*4)

__global__ void __cluster_dims__(4,1,1) __launch_bounds__(512,1)
gru_kernel(const float* __restrict__ Whh_f, const float* __restrict__ Whh_b, const float* __restrict__ Whh_q,
           const float* __restrict__ bhh_f, const float* __restrict__ bhh_b, const float* __restrict__ bhh_q)
{
    extern __shared__ float sm[];
    float* Wt   = sm;                       // 4 slices of [64 k][194]
    float* hbuf = sm + 4*WSLICE;            // 2 bufs of [4 ks][64 k][16 b]

    int tid = threadIdx.x;
    unsigned rank = ctarank_();
    int cid   = blockIdx.x >> 2;
    int chain = cid >> 3;                   // 0=f, 1=b, 2=q
    int b0    = (cid & 7) * GRU_CL_B;

    const float *Whh, *bhh, *gi;
    float* outp;
    int steps;
    if (chain == 0){ Whh = Whh_f; bhh = bhh_f; gi = g_gif; outp = g_outf; steps = S_;  }
    else if (chain == 1){ Whh = Whh_b; bhh = bhh_b; gi = g_gib; outp = g_outb; steps = S_;  }
    else { Whh = Whh_q; bhh = bhh_q; gi = g_giq; outp = g_q;    steps = TQ_; }

    // load Whh slice transposed into skewed layout:
    // Wt[ks][kloc][g*64+jj] = Whh[g*256 + rank*64 + jj][ks*64 + kloc]
    {
        int kk   = tid & 255;
        int half = tid >> 8;                // 0: rows 0..95, 1: rows 96..191
        int ksl  = kk >> 6, kloc = kk & 63;
        float* wdst = Wt + ksl*WSLICE + kloc*GRU_WT_ST;
#pragma unroll 4
        for (int rr = half*96; rr < half*96 + 96; rr++){
            int g = rr >> 6, jj = rr & 63;
            wdst[rr] = Whh[((size_t)(g*256 + (int)rank*64 + jj))*256 + kk];
        }
        for (int i = tid; i < 2*HBUFSZ; i += 512) hbuf[i] = 0.f;
    }

    int ks = tid & 3;                       // k-slice (64 k each)
    int bg = (tid >> 2) & 3;                // batch group (4 batches)
    int jp = tid >> 4;                      // 0..31 j-pair
    int j0 = jp*2;
    int jglob0 = (int)rank*64 + j0;

    // peer hbuf base addresses (mapa hoisted out of the loop)
    unsigned hb_l = smem_u32_(hbuf);
    unsigned peer0 = mapa_(hb_l, 0), peer1 = mapa_(hb_l, 1);
    unsigned peer2 = mapa_(hb_l, 2), peer3 = mapa_(hb_l, 3);

    float2 br2 = *(const float2*)(bhh       + jglob0);
    float2 bz2 = *(const float2*)(bhh + 256 + jglob0);
    float2 bn2 = *(const float2*)(bhh + 512 + jglob0);

    int bb = b0 + bg*4 + ks;                // this thread's epilogue batch
    float hp0 = 0.f, hp1 = 0.f;             // h_prev for (bb, j0) and (bb, j0+1)

    const float* wbase = Wt + ks*WSLICE + j0;
    const float* hbase = hbuf + ks*HSLICE + bg*4;

    cluster_arrive_();

    // prefetch gi for step 0 (this thread's batch)
    float2 gr0, gz0, gn0;
    {
        int pos = (chain == 1) ? (S_ - 1) : 0;
        const float* p0 = gi + ((size_t)bb*steps + pos)*G3 + jglob0;
        gr0 = *(const float2*)(p0); gz0 = *(const float2*)(p0+256); gn0 = *(const float2*)(p0+512);
    }
    cluster_wait_();

    for (int step = 0; step < steps; step++){
        int cur = step & 1, nxt = cur ^ 1;
        int pos = (chain == 1) ? (S_ - 1 - step) : step;

        // matvec over this thread's 64-k slice: 2 j x 4 batches x 3 gates
        ull aR[4] = {0,0,0,0}, aZ[4] = {0,0,0,0}, aN[4] = {0,0,0,0};
        const float* wp = wbase;
        const float* hq = hbase + cur*HBUFSZ;
#pragma unroll 4
        for (int k = 0; k < 64; k++){
            ull wr = *(const ull*)(wp);
            ull wz = *(const ull*)(wp + 64);
            ull wn = *(const ull*)(wp + 128);
            float4 h4 = *(const float4*)(hq);
            ull hd0 = dup2_(h4.x), hd1 = dup2_(h4.y), hd2 = dup2_(h4.z), hd3 = dup2_(h4.w);
            fma2_(aR[0], wr, hd0); fma2_(aR[1], wr, hd1); fma2_(aR[2], wr, hd2); fma2_(aR[3], wr, hd3);
            fma2_(aZ[0], wz, hd0); fma2_(aZ[1], wz, hd1); fma2_(aZ[2], wz, hd2); fma2_(aZ[3], wz, hd3);
            fma2_(aN[0], wn, hd0); fma2_(aN[1], wn, hd1); fma2_(aN[2], wn, hd2); fma2_(aN[3], wn, hd3);
            wp += GRU_WT_ST; hq += GRU_CL_B;
        }
        // combine the 4 k-slices (lanes differ in ks = bits 0-1): full butterfly
#pragma unroll
        for (int i = 0; i < 4; i++){
            add2_(aR[i], __shfl_xor_sync(0xffffffffu, aR[i], 1));
            add2_(aZ[i], __shfl_xor_sync(0xffffffffu, aZ[i], 1));
            add2_(aN[i], __shfl_xor_sync(0xffffffffu, aN[i], 1));
            add2_(aR[i], __shfl_xor_sync(0xffffffffu, aR[i], 2));
            add2_(aZ[i], __shfl_xor_sync(0xffffffffu, aZ[i], 2));
            add2_(aN[i], __shfl_xor_sync(0xffffffffu, aN[i], 2));
        }

        // epilogue: this thread finalizes batch bb (accumulator index = ks)
        float2 Ar = unpack2_(aR[ks]), Az = unpack2_(aZ[ks]), An = unpack2_(aN[ks]);

        float r0 = sigmoidf_(gr0.x + Ar.x + br2.x);
        float z0 = sigmoidf_(gz0.x + Az.x + bz2.x);
        float n0 = tanhf   (gn0.x + r0*(An.x + bn2.x));
        float h0 = (1.f - z0)*n0 + z0*hp0; hp0 = h0;
        float r1 = sigmoidf_(gr0.y + Ar.y + br2.y);
        float z1 = sigmoidf_(gz0.y + Az.y + bz2.y);
        float n1 = tanhf   (gn0.y + r1*(An.y + bn2.y));
        float h1 = (1.f - z1)*n1 + z1*hp1; hp1 = h1;

        // write outputs
        if (chain == 2){
            if (step == steps - 1)
                *(float2*)(outp + (size_t)bb*H_ + jglob0) = make_float2(h0, h1);
        } else {
            *(float2*)(outp + ((size_t)bb*S_ + pos)*H_ + jglob0) = make_float2(h0, h1);
        }

        // broadcast h (2 j x 1 batch) to all 4 CTAs' hbuf[nxt], slice = rank
        {
            unsigned off0 = (unsigned)((nxt*HBUFSZ + (int)rank*HSLICE + j0*GRU_CL_B + (bg*4 + ks))*4);
            unsigned off1 = off0 + GRU_CL_B*4;
            st_cluster_f32_(peer0 + off0, h0); st_cluster_f32_(peer0 + off1, h1);
            st_cluster_f32_(peer1 + off0, h0); st_cluster_f32_(peer1 + off1, h1);
            st_cluster_f32_(peer2 + off0, h0); st_cluster_f32_(peer2 + off1, h1);
            st_cluster_f32_(peer3 + off0, h0); st_cluster_f32_(peer3 + off1, h1);
        }
        cluster_arrive_();

        // prefetch gi for next step (overlaps peer skew)
        if (step + 1 < steps){
            int np = (chain == 1) ? (S_ - 2 - step) : (step + 1);
            const float* p0 = gi + ((size_t)bb*steps + np)*G3 + jglob0;
            gr0 = *(const float2*)(p0); gz0 = *(const float2*)(p0+256); gn0 = *(const float2*)(p0+512);
        }
        cluster_wait_();
    }
}

// ---------------- 4) attention + read + tanh(q*read) ----------------
__global__ void attn_kernel(){
    int b = blockIdx.x, h = threadIdx.x;
    __shared__ float en[S_];
    __shared__ float red[8];
    float qh = g_q[(size_t)b*H_ + h];
    int lane = h & 31, wid = h >> 5;
    for (int s = 0; s < S_; s++){
        float f = g_outf[((size_t)b*S_ + s)*H_ + h] + g_outb[((size_t)b*S_ + s)*H_ + h];
        float p = f * qh;
#pragma unroll
        for (int o = 16; o; o >>= 1) p += __shfl_xor_sync(0xffffffffu, p, o);
        if (lane == 0) red[wid] = p;
        __syncthreads();
        if (h < 8){
            float t = red[h];
            t += __shfl_xor_sync(0xffu, t, 4);
            t += __shfl_xor_sync(0xffu, t, 2);
            t += __shfl_xor_sync(0xffu, t, 1);
            if (h == 0) en[s] = t;
        }
        __syncthreads();
    }
    float mx = -1e30f;
    for (int s = 0; s < S_; s++) mx = fmaxf(mx, en[s]);
    float sum = 0.f;
    for (int s = 0; s < S_; s++) sum += expf(en[s] - mx);
    float inv = 1.f / sum;
    float rd = 0.f;
    for (int s = 0; s < S_; s++){
        float a = expf(en[s] - mx) * inv;
        rd += a * (g_outf[((size_t)b*S_ + s)*H_ + h] + g_outb[((size_t)b*S_ + s)*H_ + h]);
    }
    g_af[(size_t)b*H_ + h] = tanhf(qh * rd);
}

// ---------------- launch ----------------
extern "C" void kernel_launch(void* const* d_in, const int* in_sizes, int n_in,
                              void* d_out, int out_size)
{
    const int*   contexts  = (const int*)  d_in[0];
    const int*   questions = (const int*)  d_in[1];
    const float* emb       = (const float*)d_in[2];
    const float* Wih_f     = (const float*)d_in[3];
    const float* Whh_f     = (const float*)d_in[4];
    const float* bih_f     = (const float*)d_in[5];
    const float* bhh_f     = (const float*)d_in[6];
    const float* Wih_b     = (const float*)d_in[7];
    const float* Whh_b     = (const float*)d_in[8];
    const float* bih_b     = (const float*)d_in[9];
    const float* bhh_b     = (const float*)d_in[10];
    const float* Wih_q     = (const float*)d_in[11];
    const float* Whh_q     = (const float*)d_in[12];
    const float* bih_q     = (const float*)d_in[13];
    const float* bhh_q     = (const float*)d_in[14];
    const float* Wo        = (const float*)d_in[15];
    const float* bo        = (const float*)d_in[16];
    float* out = (float*)d_out;

    float *p_ctx, *p_qemb, *p_gif, *p_gib, *p_giq, *p_af;
    cudaGetSymbolAddress((void**)&p_ctx,  g_ctx);
    cudaGetSymbolAddress((void**)&p_qemb, g_qemb);
    cudaGetSymbolAddress((void**)&p_gif,  g_gif);
    cudaGetSymbolAddress((void**)&p_gib,  g_gib);
    cudaGetSymbolAddress((void**)&p_giq,  g_giq);
    cudaGetSymbolAddress((void**)&p_af,   g_af);

    cudaFuncSetAttribute(gru_kernel, cudaFuncAttributeMaxDynamicSharedMemorySize, GRU_SMEM_BYTES);

    // 1) embeddings
    embed_pe_kernel<<<B_*S_, 256>>>(contexts, emb);
    qemb_kernel<<<B_*TQ_, 256>>>(questions, emb);

    // 2) all three input-gate GEMMs in one launch (z selects problem)
    gemm3_kernel<<<dim3(B_*S_/128, G3/64, 3), 256>>>(
        p_ctx,  Wih_f, bih_f, p_gif, B_*S_,
        p_ctx,  Wih_b, bih_b, p_gib, B_*S_,
        p_qemb, Wih_q, bih_q, p_giq, B_*TQ_);

    // 3) all three GRU chains concurrently (24 clusters x 4 CTAs)
    gru_kernel<<<96, 512, GRU_SMEM_BYTES>>>(Whh_f, Whh_b, Whh_q, bhh_f, bhh_b, bhh_q);

    // 4) attention + read + tanh
    attn_kernel<<<B_, 256>>>();

    // 5) vocab projection: out = af @ Wo^T + bo
    gemm_atb<<<dim3(1, (V_ + 63)/64), 256>>>(p_af, Wo, bo, out, V_);
}

// round 7
// speedup vs baseline: 1.8963x; 1.0699x over previous
#include <cuda_runtime.h>
#include <cuda_bf16.h>
#include <cstdint>
#include <cstdio>

#define B_  128
#define S_  50
#define T_  32
#define TQ_ 32
#define H_  256
#define V_  50257
#define G3  768
#define KTOT 768            // split-bf16 tripled K
#define VPAD 50304          // V_ rounded up to 64

typedef unsigned long long ull;
typedef __nv_bfloat16 bf16;

// ---------------- scratch (device globals; no allocation) ----------------
__device__ bf16  g_ctxA[B_*S_*KTOT];     // A' for ctx: [hi|hi|lo]
__device__ bf16  g_qA  [B_*TQ_*KTOT];    // A' for question tokens
__device__ bf16  g_afA [B_*KTOT];        // A' for attended feature
__device__ bf16  g_wfA [G3*KTOT];        // W' = [hi|lo|hi]
__device__ bf16  g_wbA [G3*KTOT];
__device__ bf16  g_wqA [G3*KTOT];
__device__ bf16  g_woA [VPAD*KTOT];      // 77 MB
__device__ float g_gif [B_*S_*G3];
__device__ float g_gib [B_*S_*G3];
__device__ float g_giq [B_*TQ_*G3];
__device__ float g_outf[B_*S_*H_];
__device__ float g_outb[B_*S_*H_];
__device__ float g_q   [B_*H_];

// ---------------- helpers ----------------
__device__ __forceinline__ float sigmoidf_(float x){ return 1.0f/(1.0f+expf(-x)); }

__device__ __forceinline__ void split_bf16_(float v, bf16& hi, bf16& lo){
    hi = __float2bfloat16(v);
    lo = __float2bfloat16(v - __bfloat162float(hi));
}
__device__ __forceinline__ ull dup2_(float v){
    ull r; asm("mov.b64 %0, {%1, %1};" : "=l"(r) : "f"(v)); return r;
}
__device__ __forceinline__ void fma2_(ull& d, ull a, ull b){
    asm("fma.rn.f32x2 %0, %1, %2, %0;" : "+l"(d) : "l"(a), "l"(b));
}
__device__ __forceinline__ void add2_(ull& d, ull o){
    asm("add.rn.f32x2 %0, %0, %1;" : "+l"(d) : "l"(o));
}
__device__ __forceinline__ float2 unpack2_(ull v){
    float2 r; asm("mov.b64 {%0, %1}, %2;" : "=f"(r.x), "=f"(r.y) : "l"(v)); return r;
}
__device__ __forceinline__ unsigned smem_u32_(const void* p){
    unsigned r;
    asm("{ .reg .u64 t; cvta.to.shared.u64 t, %1; cvt.u32.u64 %0, t; }" : "=r"(r) : "l"(p));
    return r;
}
__device__ __forceinline__ unsigned mapa_(unsigned laddr, unsigned rank){
    unsigned r;
    asm("mapa.shared::cluster.u32 %0, %1, %2;" : "=r"(r) : "r"(laddr), "r"(rank));
    return r;
}
__device__ __forceinline__ void st_cluster_f32_(unsigned addr, float a){
    asm volatile("st.shared::cluster.f32 [%0], %1;" :: "r"(addr), "f"(a) : "memory");
}
__device__ __forceinline__ void cluster_arrive_(){
    asm volatile("barrier.cluster.arrive.aligned;" ::: "memory");
}
__device__ __forceinline__ void cluster_wait_(){
    asm volatile("barrier.cluster.wait.aligned;" ::: "memory");
}
__device__ __forceinline__ unsigned ctarank_(){
    unsigned r; asm("mov.u32 %0, %%cluster_ctarank;" : "=r"(r)); return r;
}
__device__ __forceinline__ void mma_bf16_(float4& d, const unsigned a[4], const unsigned b[2]){
    asm("mma.sync.aligned.m16n8k16.row.col.f32.bf16.bf16.f32 "
        "{%0,%1,%2,%3}, {%4,%5,%6,%7}, {%8,%9}, {%0,%1,%2,%3};"
        : "+f"(d.x), "+f"(d.y), "+f"(d.z), "+f"(d.w)
        : "r"(a[0]), "r"(a[1]), "r"(a[2]), "r"(a[3]), "r"(b[0]), "r"(b[1]));
}

// ---------------- 1) embedding + position encoding -> split-bf16 A' ----------------
__global__ void embed_pe_kernel(const int* __restrict__ ctx, const float* __restrict__ emb){
    int bs = blockIdx.x;          // b*S_ + s
    int h  = threadIdx.x;         // 0..255
    __shared__ int ids[T_];
    if (h < T_) ids[h] = ctx[bs*T_ + h];
    __syncthreads();
    float e = (float)h * (1.0f/255.0f);
    float acc = 0.f;
#pragma unroll
    for (int t = 0; t < T_; t++){
        float s = (float)t * (1.0f/31.0f);
        float l = 1.0f - s - e*(1.0f - 2.0f*s);
        acc += emb[(size_t)ids[t]*H_ + h] * l;
    }
    bf16 hi, lo; split_bf16_(acc, hi, lo);
    bf16* dst = g_ctxA + (size_t)bs*KTOT;
    dst[h] = hi; dst[h + 256] = hi; dst[h + 512] = lo;
}

__global__ void qemb_kernel(const int* __restrict__ q, const float* __restrict__ emb){
    int i = blockIdx.x;           // b*TQ_ + t
    int h = threadIdx.x;
    float v = emb[(size_t)q[i]*H_ + h];
    bf16 hi, lo; split_bf16_(v, hi, lo);
    bf16* dst = g_qA + (size_t)i*KTOT;
    dst[h] = hi; dst[h + 256] = hi; dst[h + 512] = lo;
}

// ---------------- weight split kernels ----------------
__global__ void convW3_kernel(const float* __restrict__ Wf, const float* __restrict__ Wb,
                              const float* __restrict__ Wq){
    int n = blockIdx.x;           // 0..767
    int k = threadIdx.x;          // 0..255
    const float* W; bf16* D;
    if (blockIdx.y == 0){ W = Wf; D = g_wfA; }
    else if (blockIdx.y == 1){ W = Wb; D = g_wbA; }
    else { W = Wq; D = g_wqA; }
    float v = W[(size_t)n*256 + k];
    bf16 hi, lo; split_bf16_(v, hi, lo);
    bf16* dst = D + (size_t)n*KTOT;
    dst[k] = hi; dst[k + 256] = lo; dst[k + 512] = hi;
}

__global__ void convWo_kernel(const float* __restrict__ Wo){
    int n = blockIdx.x;           // 0..VPAD-1
    int k = threadIdx.x;
    float v = (n < V_) ? Wo[(size_t)n*256 + k] : 0.f;
    bf16 hi, lo; split_bf16_(v, hi, lo);
    bf16* dst = g_woA + (size_t)n*KTOT;
    dst[k] = hi; dst[k + 256] = lo; dst[k + 512] = hi;
}

// ---------------- 2) split-bf16 tensor GEMM ----------------
// C[m,n] = sum_{k<768} A'[m,k]*W'[n,k] + bias[n]  (= fp32-accurate A.W^T)
// CTA: 256 threads (8 warps, 4x2), tile 128m x 64n, K-chunk 64.
#define AST 72   // smem row stride (bf16 elems): 64 data + 8 pad -> conflict-free
__device__ __forceinline__ void bgemm_body(const bf16* __restrict__ A,
                                           const bf16* __restrict__ W,
                                           const float* __restrict__ bias,
                                           float* __restrict__ C,
                                           int Nv, int bm, int bn)
{
    __shared__ bf16 As[128*AST];
    __shared__ bf16 Bs[64*AST];
    int tid = threadIdx.x;
    int lane = tid & 31, wid = tid >> 5;
    int wm = (wid & 3) * 32;     // warp m offset
    int wn = (wid >> 2) * 32;    // warp n offset

    float4 acc[2][4];
#pragma unroll
    for (int i = 0; i < 2; i++)
#pragma unroll
        for (int j = 0; j < 4; j++) acc[i][j] = make_float4(0.f,0.f,0.f,0.f);

    for (int k0 = 0; k0 < KTOT; k0 += 64){
#pragma unroll
        for (int i = 0; i < 4; i++){
            int idx = tid + i*256;           // 1024 chunks of 16B
            int r = idx >> 3, ck = idx & 7;
            uint4 v = *(const uint4*)(A + (size_t)(bm + r)*KTOT + k0 + ck*8);
            *(uint4*)(As + r*AST + ck*8) = v;
        }
#pragma unroll
        for (int i = 0; i < 2; i++){
            int idx = tid + i*256;           // 512 chunks
            int r = idx >> 3, ck = idx & 7;
            uint4 v = *(const uint4*)(W + (size_t)(bn + r)*KTOT + k0 + ck*8);
            *(uint4*)(Bs + r*AST + ck*8) = v;
        }
        __syncthreads();
        int r = lane >> 2, c2 = (lane & 3) * 2;
#pragma unroll
        for (int kk = 0; kk < 4; kk++){      // 4 x k16
            unsigned af[2][4], bfr[4][2];
#pragma unroll
            for (int i = 0; i < 2; i++){
                const bf16* ab = As + (wm + i*16)*AST + kk*16;
                af[i][0] = *(const unsigned*)(ab + (r    )*AST + c2    );
                af[i][1] = *(const unsigned*)(ab + (r + 8)*AST + c2    );
                af[i][2] = *(const unsigned*)(ab + (r    )*AST + c2 + 8);
                af[i][3] = *(const unsigned*)(ab + (r + 8)*AST + c2 + 8);
            }
#pragma unroll
            for (int j = 0; j < 4; j++){
                const bf16* bb = Bs + (wn + j*8)*AST + kk*16;
                bfr[j][0] = *(const unsigned*)(bb + r*AST + c2    );
                bfr[j][1] = *(const unsigned*)(bb + r*AST + c2 + 8);
            }
#pragma unroll
            for (int i = 0; i < 2; i++)
#pragma unroll
                for (int j = 0; j < 4; j++)
                    mma_bf16_(acc[i][j], af[i], bfr[j]);
        }
        __syncthreads();
    }
    // epilogue (+bias), C row stride = Nv.
    // NOTE: when Nv is odd (vocab = 50257), float2 stores would be misaligned
    // on odd rows -> use scalar stores on that path.
    int r = lane >> 2, c2 = (lane & 3) * 2;
    bool even_stride = ((Nv & 1) == 0);
#pragma unroll
    for (int i = 0; i < 2; i++){
        int m0 = bm + wm + i*16 + r;
#pragma unroll
        for (int j = 0; j < 4; j++){
            int n0 = bn + wn + j*8 + c2;
            if (n0 < Nv){
                float4 a = acc[i][j];
                float b0 = bias[n0];
                if (n0 + 1 < Nv){
                    float b1 = bias[n0+1];
                    if (even_stride){
                        *(float2*)(C + (size_t)m0*Nv + n0)     = make_float2(a.x + b0, a.y + b1);
                        *(float2*)(C + (size_t)(m0+8)*Nv + n0) = make_float2(a.z + b0, a.w + b1);
                    } else {
                        C[(size_t)m0*Nv + n0]         = a.x + b0;
                        C[(size_t)m0*Nv + n0 + 1]     = a.y + b1;
                        C[(size_t)(m0+8)*Nv + n0]     = a.z + b0;
                        C[(size_t)(m0+8)*Nv + n0 + 1] = a.w + b1;
                    }
                } else {
                    C[(size_t)m0*Nv + n0]     = a.x + b0;
                    C[(size_t)(m0+8)*Nv + n0] = a.z + b0;
                }
            }
        }
    }
}

__global__ __launch_bounds__(256) void bgemm3_kernel(
    const float* bias_f, const float* bias_b, const float* bias_q)
{
    const bf16 *A, *W; const float* bias; float* C; int M;
    if (blockIdx.z == 0){ A = g_ctxA; W = g_wfA; bias = bias_f; C = g_gif; M = B_*S_; }
    else if (blockIdx.z == 1){ A = g_ctxA; W = g_wbA; bias = bias_b; C = g_gib; M = B_*S_; }
    else { A = g_qA; W = g_wqA; bias = bias_q; C = g_giq; M = B_*TQ_; }
    int bm = blockIdx.x * 128;
    if (bm >= M) return;
    bgemm_body(A, W, bias, C, G3, bm, blockIdx.y * 64);
}

__global__ __launch_bounds__(256) void bgemm_vocab_kernel(const float* __restrict__ bo,
                                                          float* __restrict__ out)
{
    bgemm_body(g_afA, g_woA, bo, out, V_, 0, blockIdx.y * 64);
}

// ---------------- 3) GRU recurrences (R5 known-good) ----------------
#define GRU_CL_B   16
#define GRU_WT_ST  194
#define WSLICE     (64*GRU_WT_ST + 8)
#define HSLICE     (64*GRU_CL_B + 16)
#define HBUFSZ     (4*HSLICE)
#define GRU_SMEM_FLOATS (4*WSLICE + 2*HBUFSZ)
#define GRU_SMEM_BYTES  (GRU_SMEM_FLOATS*4)

__global__ void __cluster_dims__(4,1,1) __launch_bounds__(512,1)
gru_kernel(const float* __restrict__ Whh_f, const float* __restrict__ Whh_b, const float* __restrict__ Whh_q,
           const float* __restrict__ bhh_f, const float* __restrict__ bhh_b, const float* __restrict__ bhh_q)
{
    extern __shared__ float sm[];
    float* Wt   = sm;
    float* hbuf = sm + 4*WSLICE;

    int tid = threadIdx.x;
    unsigned rank = ctarank_();
    int cid   = blockIdx.x >> 2;
    int chain = cid >> 3;
    int b0    = (cid & 7) * GRU_CL_B;

    const float *Whh, *bhh, *gi;
    float* outp;
    int steps;
    if (chain == 0){ Whh = Whh_f; bhh = bhh_f; gi = g_gif; outp = g_outf; steps = S_;  }
    else if (chain == 1){ Whh = Whh_b; bhh = bhh_b; gi = g_gib; outp = g_outb; steps = S_;  }
    else { Whh = Whh_q; bhh = bhh_q; gi = g_giq; outp = g_q;    steps = TQ_; }

    {
        int kk   = tid & 255;
        int half = tid >> 8;
        int ksl  = kk >> 6, kloc = kk & 63;
        float* wdst = Wt + ksl*WSLICE + kloc*GRU_WT_ST;
#pragma unroll 4
        for (int rr = half*96; rr < half*96 + 96; rr++){
            int g = rr >> 6, jj = rr & 63;
            wdst[rr] = Whh[((size_t)(g*256 + (int)rank*64 + jj))*256 + kk];
        }
        for (int i = tid; i < 2*HBUFSZ; i += 512) hbuf[i] = 0.f;
    }

    int ks = tid & 3;
    int bg = (tid >> 2) & 3;
    int jp = tid >> 4;
    int j0 = jp*2;
    int jglob0 = (int)rank*64 + j0;

    unsigned hb_l = smem_u32_(hbuf);
    unsigned peer0 = mapa_(hb_l, 0), peer1 = mapa_(hb_l, 1);
    unsigned peer2 = mapa_(hb_l, 2), peer3 = mapa_(hb_l, 3);

    float2 br2 = *(const float2*)(bhh       + jglob0);
    float2 bz2 = *(const float2*)(bhh + 256 + jglob0);
    float2 bn2 = *(const float2*)(bhh + 512 + jglob0);

    int bb = b0 + bg*4 + ks;
    float hp0 = 0.f, hp1 = 0.f;

    const float* wbase = Wt + ks*WSLICE + j0;
    const float* hbase = hbuf + ks*HSLICE + bg*4;

    cluster_arrive_();

    float2 gr0, gz0, gn0;
    {
        int pos = (chain == 1) ? (S_ - 1) : 0;
        const float* p0 = gi + ((size_t)bb*steps + pos)*G3 + jglob0;
        gr0 = *(const float2*)(p0); gz0 = *(const float2*)(p0+256); gn0 = *(const float2*)(p0+512);
    }
    cluster_wait_();

    for (int step = 0; step < steps; step++){
        int cur = step & 1, nxt = cur ^ 1;
        int pos = (chain == 1) ? (S_ - 1 - step) : step;

        ull aR[4] = {0,0,0,0}, aZ[4] = {0,0,0,0}, aN[4] = {0,0,0,0};
        const float* wp = wbase;
        const float* hq = hbase + cur*HBUFSZ;
#pragma unroll 4
        for (int k = 0; k < 64; k++){
            ull wr = *(const ull*)(wp);
            ull wz = *(const ull*)(wp + 64);
            ull wn = *(const ull*)(wp + 128);
            float4 h4 = *(const float4*)(hq);
            ull hd0 = dup2_(h4.x), hd1 = dup2_(h4.y), hd2 = dup2_(h4.z), hd3 = dup2_(h4.w);
            fma2_(aR[0], wr, hd0); fma2_(aR[1], wr, hd1); fma2_(aR[2], wr, hd2); fma2_(aR[3], wr, hd3);
            fma2_(aZ[0], wz, hd0); fma2_(aZ[1], wz, hd1); fma2_(aZ[2], wz, hd2); fma2_(aZ[3], wz, hd3);
            fma2_(aN[0], wn, hd0); fma2_(aN[1], wn, hd1); fma2_(aN[2], wn, hd2); fma2_(aN[3], wn, hd3);
            wp += GRU_WT_ST; hq += GRU_CL_B;
        }
#pragma unroll
        for (int i = 0; i < 4; i++){
            add2_(aR[i], __shfl_xor_sync(0xffffffffu, aR[i], 1));
            add2_(aZ[i], __shfl_xor_sync(0xffffffffu, aZ[i], 1));
            add2_(aN[i], __shfl_xor_sync(0xffffffffu, aN[i], 1));
            add2_(aR[i], __shfl_xor_sync(0xffffffffu, aR[i], 2));
            add2_(aZ[i], __shfl_xor_sync(0xffffffffu, aZ[i], 2));
            add2_(aN[i], __shfl_xor_sync(0xffffffffu, aN[i], 2));
        }

        float2 Ar = unpack2_(aR[ks]), Az = unpack2_(aZ[ks]), An = unpack2_(aN[ks]);

        float r0 = sigmoidf_(gr0.x + Ar.x + br2.x);
        float z0 = sigmoidf_(gz0.x + Az.x + bz2.x);
        float n0 = tanhf   (gn0.x + r0*(An.x + bn2.x));
        float h0 = (1.f - z0)*n0 + z0*hp0; hp0 = h0;
        float r1 = sigmoidf_(gr0.y + Ar.y + br2.y);
        float z1 = sigmoidf_(gz0.y + Az.y + bz2.y);
        float n1 = tanhf   (gn0.y + r1*(An.y + bn2.y));
        float h1 = (1.f - z1)*n1 + z1*hp1; hp1 = h1;

        if (chain == 2){
            if (step == steps - 1)
                *(float2*)(outp + (size_t)bb*H_ + jglob0) = make_float2(h0, h1);
        } else {
            *(float2*)(outp + ((size_t)bb*S_ + pos)*H_ + jglob0) = make_float2(h0, h1);
        }

        {
            unsigned off0 = (unsigned)((nxt*HBUFSZ + (int)rank*HSLICE + j0*GRU_CL_B + (bg*4 + ks))*4);
            unsigned off1 = off0 + GRU_CL_B*4;
            st_cluster_f32_(peer0 + off0, h0); st_cluster_f32_(peer0 + off1, h1);
            st_cluster_f32_(peer1 + off0, h0); st_cluster_f32_(peer1 + off1, h1);
            st_cluster_f32_(peer2 + off0, h0); st_cluster_f32_(peer2 + off1, h1);
            st_cluster_f32_(peer3 + off0, h0); st_cluster_f32_(peer3 + off1, h1);
        }
        cluster_arrive_();

        if (step + 1 < steps){
            int np = (chain == 1) ? (S_ - 2 - step) : (step + 1);
            const float* p0 = gi + ((size_t)bb*steps + np)*G3 + jglob0;
            gr0 = *(const float2*)(p0); gz0 = *(const float2*)(p0+256); gn0 = *(const float2*)(p0+512);
        }
        cluster_wait_();
    }
}

// ---------------- 4) attention + read + tanh(q*read) -> split-bf16 A' ----------------
__global__ void attn_kernel(){
    int b = blockIdx.x, h = threadIdx.x;
    __shared__ float en[S_];
    __shared__ float red[8];
    float qh = g_q[(size_t)b*H_ + h];
    int lane = h & 31, wid = h >> 5;
    for (int s = 0; s < S_; s++){
        float f = g_outf[((size_t)b*S_ + s)*H_ + h] + g_outb[((size_t)b*S_ + s)*H_ + h];
        float p = f * qh;
#pragma unroll
        for (int o = 16; o; o >>= 1) p += __shfl_xor_sync(0xffffffffu, p, o);
        if (lane == 0) red[wid] = p;
        __syncthreads();
        if (h < 8){
            float t = red[h];
            t += __shfl_xor_sync(0xffu, t, 4);
            t += __shfl_xor_sync(0xffu, t, 2);
            t += __shfl_xor_sync(0xffu, t, 1);
            if (h == 0) en[s] = t;
        }
        __syncthreads();
    }
    float mx = -1e30f;
    for (int s = 0; s < S_; s++) mx = fmaxf(mx, en[s]);
    float sum = 0.f;
    for (int s = 0; s < S_; s++) sum += expf(en[s] - mx);
    float inv = 1.f / sum;
    float rd = 0.f;
    for (int s = 0; s < S_; s++){
        float a = expf(en[s] - mx) * inv;
        rd += a * (g_outf[((size_t)b*S_ + s)*H_ + h] + g_outb[((size_t)b*S_ + s)*H_ + h]);
    }
    float v = tanhf(qh * rd);
    bf16 hi, lo; split_bf16_(v, hi, lo);
    bf16* dst = g_afA + (size_t)b*KTOT;
    dst[h] = hi; dst[h + 256] = hi; dst[h + 512] = lo;
}

// ---------------- launch ----------------
extern "C" void kernel_launch(void* const* d_in, const int* in_sizes, int n_in,
                              void* d_out, int out_size)
{
    const int*   contexts  = (const int*)  d_in[0];
    const int*   questions = (const int*)  d_in[1];
    const float* emb       = (const float*)d_in[2];
    const float* Wih_f     = (const float*)d_in[3];
    const float* Whh_f     = (const float*)d_in[4];
    const float* bih_f     = (const float*)d_in[5];
    const float* bhh_f     = (const float*)d_in[6];
    const float* Wih_b     = (const float*)d_in[7];
    const float* Whh_b     = (const float*)d_in[8];
    const float* bih_b     = (const float*)d_in[9];
    const float* bhh_b     = (const float*)d_in[10];
    const float* Wih_q     = (const float*)d_in[11];
    const float* Whh_q     = (const float*)d_in[12];
    const float* bih_q     = (const float*)d_in[13];
    const float* bhh_q     = (const float*)d_in[14];
    const float* Wo        = (const float*)d_in[15];
    const float* bo        = (const float*)d_in[16];
    float* out = (float*)d_out;

    cudaFuncSetAttribute(gru_kernel, cudaFuncAttributeMaxDynamicSharedMemorySize, GRU_SMEM_BYTES);

    // weight splits (independent of activations)
    convW3_kernel<<<dim3(G3, 3), 256>>>(Wih_f, Wih_b, Wih_q);
    convWo_kernel<<<VPAD, 256>>>(Wo);

    // 1) embeddings (fused split-bf16 write)
    embed_pe_kernel<<<B_*S_, 256>>>(contexts, emb);
    qemb_kernel<<<B_*TQ_, 256>>>(questions, emb);

    // 2) input-gate GEMMs on tensor cores (split-bf16, K=768)
    bgemm3_kernel<<<dim3(B_*S_/128, G3/64, 3), 256>>>(bih_f, bih_b, bih_q);

    // 3) GRU chains (24 clusters x 4 CTAs)
    gru_kernel<<<96, 512, GRU_SMEM_BYTES>>>(Whh_f, Whh_b, Whh_q, bhh_f, bhh_b, bhh_q);

    // 4) attention + read + tanh (fused split-bf16 write)
    attn_kernel<<<B_, 256>>>();

    // 5) vocab projection on tensor cores
    bgemm_vocab_kernel<<<dim3(1, VPAD/64), 256>>>(bo, out);
}

// round 8
// speedup vs baseline: 3.0117x; 1.5882x over previous
#include <cuda_runtime.h>
#include <cuda_bf16.h>
#include <cstdint>
#include <cstdio>

#define B_  128
#define S_  50
#define T_  32
#define TQ_ 32
#define H_  256
#define V_  50257
#define G3  768
#define KTOT 768            // split-bf16 tripled K (feedforward GEMMs)
#define VPAD 50304

typedef unsigned long long ull;
typedef __nv_bfloat16 bf16;

// ---------------- scratch (device globals; no allocation) ----------------
__device__ bf16  g_ctxA[B_*S_*KTOT];
__device__ bf16  g_qA  [B_*TQ_*KTOT];
__device__ bf16  g_afA [B_*KTOT];
__device__ bf16  g_wfA [G3*KTOT];
__device__ bf16  g_wbA [G3*KTOT];
__device__ bf16  g_wqA [G3*KTOT];
__device__ bf16  g_woA [VPAD*KTOT];
__device__ float g_gif [B_*S_*G3];
__device__ float g_gib [B_*S_*G3];
__device__ float g_giq [B_*TQ_*G3];
__device__ float g_outf[B_*S_*H_];
__device__ float g_outb[B_*S_*H_];
__device__ float g_q   [B_*H_];

// ---------------- helpers ----------------
__device__ __forceinline__ float sigmoidf_(float x){ return 1.0f/(1.0f+expf(-x)); }

__device__ __forceinline__ void split_bf16_(float v, bf16& hi, bf16& lo){
    hi = __float2bfloat16(v);
    lo = __float2bfloat16(v - __bfloat162float(hi));
}
__device__ __forceinline__ unsigned pack_bf2_(bf16 a, bf16 b){
    unsigned short x = *reinterpret_cast<unsigned short*>(&a);
    unsigned short y = *reinterpret_cast<unsigned short*>(&b);
    return (unsigned)x | ((unsigned)y << 16);
}
__device__ __forceinline__ unsigned smem_u32_(const void* p){
    unsigned r;
    asm("{ .reg .u64 t; cvta.to.shared.u64 t, %1; cvt.u32.u64 %0, t; }" : "=r"(r) : "l"(p));
    return r;
}
__device__ __forceinline__ unsigned mapa_(unsigned laddr, unsigned rank){
    unsigned r;
    asm("mapa.shared::cluster.u32 %0, %1, %2;" : "=r"(r) : "r"(laddr), "r"(rank));
    return r;
}
__device__ __forceinline__ void st_cluster_u32_(unsigned addr, unsigned v){
    asm volatile("st.shared::cluster.u32 [%0], %1;" :: "r"(addr), "r"(v) : "memory");
}
__device__ __forceinline__ void cluster_arrive_(){
    asm volatile("barrier.cluster.arrive.aligned;" ::: "memory");
}
__device__ __forceinline__ void cluster_wait_(){
    asm volatile("barrier.cluster.wait.aligned;" ::: "memory");
}
__device__ __forceinline__ unsigned ctarank_(){
    unsigned r; asm("mov.u32 %0, %%cluster_ctarank;" : "=r"(r)); return r;
}
__device__ __forceinline__ void mma_bf16_(float4& d, const unsigned a[4], const unsigned b[2]){
    asm("mma.sync.aligned.m16n8k16.row.col.f32.bf16.bf16.f32 "
        "{%0,%1,%2,%3}, {%4,%5,%6,%7}, {%8,%9}, {%0,%1,%2,%3};"
        : "+f"(d.x), "+f"(d.y), "+f"(d.z), "+f"(d.w)
        : "r"(a[0]), "r"(a[1]), "r"(a[2]), "r"(a[3]), "r"(b[0]), "r"(b[1]));
}

// ---------------- 1) embedding + position encoding -> split-bf16 A' ----------------
__global__ void embed_pe_kernel(const int* __restrict__ ctx, const float* __restrict__ emb){
    int bs = blockIdx.x;
    int h  = threadIdx.x;
    __shared__ int ids[T_];
    if (h < T_) ids[h] = ctx[bs*T_ + h];
    __syncthreads();
    float e = (float)h * (1.0f/255.0f);
    float acc = 0.f;
#pragma unroll
    for (int t = 0; t < T_; t++){
        float s = (float)t * (1.0f/31.0f);
        float l = 1.0f - s - e*(1.0f - 2.0f*s);
        acc += emb[(size_t)ids[t]*H_ + h] * l;
    }
    bf16 hi, lo; split_bf16_(acc, hi, lo);
    bf16* dst = g_ctxA + (size_t)bs*KTOT;
    dst[h] = hi; dst[h + 256] = hi; dst[h + 512] = lo;
}

__global__ void qemb_kernel(const int* __restrict__ q, const float* __restrict__ emb){
    int i = blockIdx.x;
    int h = threadIdx.x;
    float v = emb[(size_t)q[i]*H_ + h];
    bf16 hi, lo; split_bf16_(v, hi, lo);
    bf16* dst = g_qA + (size_t)i*KTOT;
    dst[h] = hi; dst[h + 256] = hi; dst[h + 512] = lo;
}

// ---------------- weight split kernels (feedforward) ----------------
__global__ void convW3_kernel(const float* __restrict__ Wf, const float* __restrict__ Wb,
                              const float* __restrict__ Wq){
    int n = blockIdx.x;
    int k = threadIdx.x;
    const float* W; bf16* D;
    if (blockIdx.y == 0){ W = Wf; D = g_wfA; }
    else if (blockIdx.y == 1){ W = Wb; D = g_wbA; }
    else { W = Wq; D = g_wqA; }
    float v = W[(size_t)n*256 + k];
    bf16 hi, lo; split_bf16_(v, hi, lo);
    bf16* dst = D + (size_t)n*KTOT;
    dst[k] = hi; dst[k + 256] = lo; dst[k + 512] = hi;
}

__global__ void convWo_kernel(const float* __restrict__ Wo){
    int n = blockIdx.x;
    int k = threadIdx.x;
    float v = (n < V_) ? Wo[(size_t)n*256 + k] : 0.f;
    bf16 hi, lo; split_bf16_(v, hi, lo);
    bf16* dst = g_woA + (size_t)n*KTOT;
    dst[k] = hi; dst[k + 256] = lo; dst[k + 512] = hi;
}

// ---------------- 2) split-bf16 tensor GEMM (R7 passing version) ----------------
#define AST 72
__device__ __forceinline__ void bgemm_body(const bf16* __restrict__ A,
                                           const bf16* __restrict__ W,
                                           const float* __restrict__ bias,
                                           float* __restrict__ C,
                                           int Nv, int bm, int bn)
{
    __shared__ bf16 As[128*AST];
    __shared__ bf16 Bs[64*AST];
    int tid = threadIdx.x;
    int lane = tid & 31, wid = tid >> 5;
    int wm = (wid & 3) * 32;
    int wn = (wid >> 2) * 32;

    float4 acc[2][4];
#pragma unroll
    for (int i = 0; i < 2; i++)
#pragma unroll
        for (int j = 0; j < 4; j++) acc[i][j] = make_float4(0.f,0.f,0.f,0.f);

    for (int k0 = 0; k0 < KTOT; k0 += 64){
#pragma unroll
        for (int i = 0; i < 4; i++){
            int idx = tid + i*256;
            int r = idx >> 3, ck = idx & 7;
            uint4 v = *(const uint4*)(A + (size_t)(bm + r)*KTOT + k0 + ck*8);
            *(uint4*)(As + r*AST + ck*8) = v;
        }
#pragma unroll
        for (int i = 0; i < 2; i++){
            int idx = tid + i*256;
            int r = idx >> 3, ck = idx & 7;
            uint4 v = *(const uint4*)(W + (size_t)(bn + r)*KTOT + k0 + ck*8);
            *(uint4*)(Bs + r*AST + ck*8) = v;
        }
        __syncthreads();
        int r = lane >> 2, c2 = (lane & 3) * 2;
#pragma unroll
        for (int kk = 0; kk < 4; kk++){
            unsigned af[2][4], bfr[4][2];
#pragma unroll
            for (int i = 0; i < 2; i++){
                const bf16* ab = As + (wm + i*16)*AST + kk*16;
                af[i][0] = *(const unsigned*)(ab + (r    )*AST + c2    );
                af[i][1] = *(const unsigned*)(ab + (r + 8)*AST + c2    );
                af[i][2] = *(const unsigned*)(ab + (r    )*AST + c2 + 8);
                af[i][3] = *(const unsigned*)(ab + (r + 8)*AST + c2 + 8);
            }
#pragma unroll
            for (int j = 0; j < 4; j++){
                const bf16* bb = Bs + (wn + j*8)*AST + kk*16;
                bfr[j][0] = *(const unsigned*)(bb + r*AST + c2    );
                bfr[j][1] = *(const unsigned*)(bb + r*AST + c2 + 8);
            }
#pragma unroll
            for (int i = 0; i < 2; i++)
#pragma unroll
                for (int j = 0; j < 4; j++)
                    mma_bf16_(acc[i][j], af[i], bfr[j]);
        }
        __syncthreads();
    }
    int r = lane >> 2, c2 = (lane & 3) * 2;
    bool even_stride = ((Nv & 1) == 0);
#pragma unroll
    for (int i = 0; i < 2; i++){
        int m0 = bm + wm + i*16 + r;
#pragma unroll
        for (int j = 0; j < 4; j++){
            int n0 = bn + wn + j*8 + c2;
            if (n0 < Nv){
                float4 a = acc[i][j];
                float b0 = bias[n0];
                if (n0 + 1 < Nv){
                    float b1 = bias[n0+1];
                    if (even_stride){
                        *(float2*)(C + (size_t)m0*Nv + n0)     = make_float2(a.x + b0, a.y + b1);
                        *(float2*)(C + (size_t)(m0+8)*Nv + n0) = make_float2(a.z + b0, a.w + b1);
                    } else {
                        C[(size_t)m0*Nv + n0]         = a.x + b0;
                        C[(size_t)m0*Nv + n0 + 1]     = a.y + b1;
                        C[(size_t)(m0+8)*Nv + n0]     = a.z + b0;
                        C[(size_t)(m0+8)*Nv + n0 + 1] = a.w + b1;
                    }
                } else {
                    C[(size_t)m0*Nv + n0]     = a.x + b0;
                    C[(size_t)(m0+8)*Nv + n0] = a.z + b0;
                }
            }
        }
    }
}

__global__ __launch_bounds__(256) void bgemm3_kernel(
    const float* bias_f, const float* bias_b, const float* bias_q)
{
    const bf16 *A, *W; const float* bias; float* C; int M;
    if (blockIdx.z == 0){ A = g_ctxA; W = g_wfA; bias = bias_f; C = g_gif; M = B_*S_; }
    else if (blockIdx.z == 1){ A = g_ctxA; W = g_wbA; bias = bias_b; C = g_gib; M = B_*S_; }
    else { A = g_qA; W = g_wqA; bias = bias_q; C = g_giq; M = B_*TQ_; }
    int bm = blockIdx.x * 128;
    if (bm >= M) return;
    bgemm_body(A, W, bias, C, G3, bm, blockIdx.y * 64);
}

__global__ __launch_bounds__(256) void bgemm_vocab_kernel(const float* __restrict__ bo,
                                                          float* __restrict__ out)
{
    bgemm_body(g_afA, g_woA, bo, out, V_, 0, blockIdx.y * 64);
}

// ---------------- 3) GRU recurrence on TENSOR CORES (split-bf16 mma) ----------------
// Cluster of 4 CTAs, 16 batches/cluster, CTA owns 64 hidden j (192 gate rows).
// 24 clusters: f(0..7), b(8..15), q(16..23). 256 threads (8 warps, warp = 8-j block).
// smem: W_hi[192][264] + W_lo[192][264] bf16 (198KB), hbuf[16][520] bf16 (hi|lo, 16.6KB).
// Per step per warp: 144 mma.m16n8k16 (48 k-tiles x 3 gate n-tiles).
#define GRU_WST 264
#define GRU_HST 520
#define GRU_WPLANE (192*GRU_WST)
#define GRU_SMEM_BF16 (2*GRU_WPLANE + 16*GRU_HST)
#define GRU_SMEM_BYTES (GRU_SMEM_BF16*2)

__global__ void __cluster_dims__(4,1,1) __launch_bounds__(256,1)
gru_kernel(const float* __restrict__ Whh_f, const float* __restrict__ Whh_b, const float* __restrict__ Whh_q,
           const float* __restrict__ bhh_f, const float* __restrict__ bhh_b, const float* __restrict__ bhh_q)
{
    extern __shared__ bf16 smb[];
    bf16* Whi  = smb;                    // [192][264]
    bf16* Wlo  = smb + GRU_WPLANE;       // [192][264]
    bf16* hbuf = smb + 2*GRU_WPLANE;     // [16][520]: k 0-255 = hi, 256-511 = lo

    int tid  = threadIdx.x;
    int lane = tid & 31, w = tid >> 5;   // w = j-block 0..7
    unsigned rank = ctarank_();
    int cid   = blockIdx.x >> 2;
    int chain = cid >> 3;
    int b0    = (cid & 7) * 16;

    const float *Whh, *bhh, *gi;
    float* outp;
    int steps;
    if (chain == 0){ Whh = Whh_f; bhh = bhh_f; gi = g_gif; outp = g_outf; steps = S_;  }
    else if (chain == 1){ Whh = Whh_b; bhh = bhh_b; gi = g_gib; outp = g_outb; steps = S_;  }
    else { Whh = Whh_q; bhh = bhh_q; gi = g_giq; outp = g_q;    steps = TQ_; }

    // ---- load + split Whh slice: rows {g*256 + rank*64 + jj} -> local row g*64+jj
    {
#pragma unroll 4
        for (int rr = 0; rr < 192; rr++){
            int grow = (rr >> 6)*256 + (int)rank*64 + (rr & 63);
            float v = Whh[(size_t)grow*256 + tid];
            bf16 hi, lo; split_bf16_(v, hi, lo);
            Whi[rr*GRU_WST + tid] = hi;
            Wlo[rr*GRU_WST + tid] = lo;
        }
        unsigned* hz = (unsigned*)hbuf;
        for (int i = tid; i < 16*GRU_HST/2; i += 256) hz[i] = 0u;
    }

    // ---- fragment geometry
    int r  = lane >> 2;                  // 0..7: batch (and +8), B-row within n-tile
    int c2 = (lane & 3) * 2;             // k-pair offset / j-pair offset
    int jglob0 = (int)rank*64 + w*8 + c2;

    const bf16* hA  = hbuf + r*GRU_HST + c2;         // A frag base (row r; +8 row below)
    const bf16* Bhr = Whi + (      w*8 + r)*GRU_WST + c2;
    const bf16* Bhz = Whi + ( 64 + w*8 + r)*GRU_WST + c2;
    const bf16* Bhn = Whi + (128 + w*8 + r)*GRU_WST + c2;
    const bf16* Blr = Wlo + (      w*8 + r)*GRU_WST + c2;
    const bf16* Blz = Wlo + ( 64 + w*8 + r)*GRU_WST + c2;
    const bf16* Bln = Wlo + (128 + w*8 + r)*GRU_WST + c2;

    unsigned hb_l = smem_u32_(hbuf);
    unsigned peer0 = mapa_(hb_l, 0), peer1 = mapa_(hb_l, 1);
    unsigned peer2 = mapa_(hb_l, 2), peer3 = mapa_(hb_l, 3);

    float2 br2 = *(const float2*)(bhh       + jglob0);
    float2 bz2 = *(const float2*)(bhh + 256 + jglob0);
    float2 bn2 = *(const float2*)(bhh + 512 + jglob0);

    int bbA = b0 + r, bbB = b0 + r + 8;  // this thread's two batches
    float hpA0 = 0.f, hpA1 = 0.f, hpB0 = 0.f, hpB1 = 0.f;

    cluster_arrive_();
    // prefetch gi for step 0
    float2 grA, gzA, gnA, grB, gzB, gnB;
    {
        int pos = (chain == 1) ? (S_ - 1) : 0;
        const float* pA = gi + ((size_t)bbA*steps + pos)*G3 + jglob0;
        const float* pB = gi + ((size_t)bbB*steps + pos)*G3 + jglob0;
        grA = *(const float2*)(pA); gzA = *(const float2*)(pA+256); gnA = *(const float2*)(pA+512);
        grB = *(const float2*)(pB); gzB = *(const float2*)(pB+256); gnB = *(const float2*)(pB+512);
    }
    cluster_wait_();

    for (int step = 0; step < steps; step++){
        int pos = (chain == 1) ? (S_ - 1 - step) : step;

        float4 accR = make_float4(0.f,0.f,0.f,0.f);
        float4 accZ = make_float4(0.f,0.f,0.f,0.f);
        float4 accN = make_float4(0.f,0.f,0.f,0.f);

        // pass 1: A = h_hi (k 0-255), B = W_hi then W_lo
#pragma unroll 4
        for (int kt = 0; kt < 16; kt++){
            int k0 = kt*16;
            unsigned af[4];
            af[0] = *(const unsigned*)(hA + k0);
            af[1] = *(const unsigned*)(hA + 8*GRU_HST + k0);
            af[2] = *(const unsigned*)(hA + k0 + 8);
            af[3] = *(const unsigned*)(hA + 8*GRU_HST + k0 + 8);
            unsigned bf_[2];
            bf_[0] = *(const unsigned*)(Bhr + k0); bf_[1] = *(const unsigned*)(Bhr + k0 + 8);
            mma_bf16_(accR, af, bf_);
            bf_[0] = *(const unsigned*)(Bhz + k0); bf_[1] = *(const unsigned*)(Bhz + k0 + 8);
            mma_bf16_(accZ, af, bf_);
            bf_[0] = *(const unsigned*)(Bhn + k0); bf_[1] = *(const unsigned*)(Bhn + k0 + 8);
            mma_bf16_(accN, af, bf_);
            bf_[0] = *(const unsigned*)(Blr + k0); bf_[1] = *(const unsigned*)(Blr + k0 + 8);
            mma_bf16_(accR, af, bf_);
            bf_[0] = *(const unsigned*)(Blz + k0); bf_[1] = *(const unsigned*)(Blz + k0 + 8);
            mma_bf16_(accZ, af, bf_);
            bf_[0] = *(const unsigned*)(Bln + k0); bf_[1] = *(const unsigned*)(Bln + k0 + 8);
            mma_bf16_(accN, af, bf_);
        }
        // pass 2: A = h_lo (k 256-511), B = W_hi
#pragma unroll 4
        for (int kt = 0; kt < 16; kt++){
            int k0 = kt*16;
            int ka = 256 + k0;
            unsigned af[4];
            af[0] = *(const unsigned*)(hA + ka);
            af[1] = *(const unsigned*)(hA + 8*GRU_HST + ka);
            af[2] = *(const unsigned*)(hA + ka + 8);
            af[3] = *(const unsigned*)(hA + 8*GRU_HST + ka + 8);
            unsigned bf_[2];
            bf_[0] = *(const unsigned*)(Bhr + k0); bf_[1] = *(const unsigned*)(Bhr + k0 + 8);
            mma_bf16_(accR, af, bf_);
            bf_[0] = *(const unsigned*)(Bhz + k0); bf_[1] = *(const unsigned*)(Bhz + k0 + 8);
            mma_bf16_(accZ, af, bf_);
            bf_[0] = *(const unsigned*)(Bhn + k0); bf_[1] = *(const unsigned*)(Bhn + k0 + 8);
            mma_bf16_(accN, af, bf_);
        }

        // reads of hbuf are done -> signal; epilogue math overlaps barrier
        cluster_arrive_();

        // fragment -> (batch, j): .x=(bbA,j0) .y=(bbA,j1) .z=(bbB,j0) .w=(bbB,j1)
        float rA0 = sigmoidf_(grA.x + accR.x + br2.x);
        float zA0 = sigmoidf_(gzA.x + accZ.x + bz2.x);
        float nA0 = tanhf   (gnA.x + rA0*(accN.x + bn2.x));
        float hA0 = (1.f - zA0)*nA0 + zA0*hpA0; hpA0 = hA0;
        float rA1 = sigmoidf_(grA.y + accR.y + br2.y);
        float zA1 = sigmoidf_(gzA.y + accZ.y + bz2.y);
        float nA1 = tanhf   (gnA.y + rA1*(accN.y + bn2.y));
        float hA1 = (1.f - zA1)*nA1 + zA1*hpA1; hpA1 = hA1;
        float rB0 = sigmoidf_(grB.x + accR.z + br2.x);
        float zB0 = sigmoidf_(gzB.x + accZ.z + bz2.x);
        float nB0 = tanhf   (gnB.x + rB0*(accN.z + bn2.x));
        float hB0 = (1.f - zB0)*nB0 + zB0*hpB0; hpB0 = hB0;
        float rB1 = sigmoidf_(grB.y + accR.w + br2.y);
        float zB1 = sigmoidf_(gzB.y + accZ.w + bz2.y);
        float nB1 = tanhf   (gnB.y + rB1*(accN.w + bn2.y));
        float hB1 = (1.f - zB1)*nB1 + zB1*hpB1; hpB1 = hB1;

        // split for broadcast
        bf16 hiA0, loA0, hiA1, loA1, hiB0, loB0, hiB1, loB1;
        split_bf16_(hA0, hiA0, loA0); split_bf16_(hA1, hiA1, loA1);
        split_bf16_(hB0, hiB0, loB0); split_bf16_(hB1, hiB1, loB1);
        unsigned uAhi = pack_bf2_(hiA0, hiA1), uAlo = pack_bf2_(loA0, loA1);
        unsigned uBhi = pack_bf2_(hiB0, hiB1), uBlo = pack_bf2_(loB0, loB1);

        // wait: all CTAs finished reading hbuf -> safe to overwrite
        cluster_wait_();

        unsigned offAhi = (unsigned)((r*GRU_HST + jglob0)*2);
        unsigned offAlo = offAhi + 256*2;
        unsigned offBhi = (unsigned)(((r+8)*GRU_HST + jglob0)*2);
        unsigned offBlo = offBhi + 256*2;
        st_cluster_u32_(peer0 + offAhi, uAhi); st_cluster_u32_(peer0 + offAlo, uAlo);
        st_cluster_u32_(peer0 + offBhi, uBhi); st_cluster_u32_(peer0 + offBlo, uBlo);
        st_cluster_u32_(peer1 + offAhi, uAhi); st_cluster_u32_(peer1 + offAlo, uAlo);
        st_cluster_u32_(peer1 + offBhi, uBhi); st_cluster_u32_(peer1 + offBlo, uBlo);
        st_cluster_u32_(peer2 + offAhi, uAhi); st_cluster_u32_(peer2 + offAlo, uAlo);
        st_cluster_u32_(peer2 + offBhi, uBhi); st_cluster_u32_(peer2 + offBlo, uBlo);
        st_cluster_u32_(peer3 + offAhi, uAhi); st_cluster_u32_(peer3 + offAlo, uAlo);
        st_cluster_u32_(peer3 + offBhi, uBhi); st_cluster_u32_(peer3 + offBlo, uBlo);

        cluster_arrive_();

        // outputs + next-step gi prefetch overlap the barrier
        if (chain == 2){
            if (step == steps - 1){
                *(float2*)(outp + (size_t)bbA*H_ + jglob0) = make_float2(hA0, hA1);
                *(float2*)(outp + (size_t)bbB*H_ + jglob0) = make_float2(hB0, hB1);
            }
        } else {
            *(float2*)(outp + ((size_t)bbA*S_ + pos)*H_ + jglob0) = make_float2(hA0, hA1);
            *(float2*)(outp + ((size_t)bbB*S_ + pos)*H_ + jglob0) = make_float2(hB0, hB1);
        }
        if (step + 1 < steps){
            int np = (chain == 1) ? (S_ - 2 - step) : (step + 1);
            const float* pA = gi + ((size_t)bbA*steps + np)*G3 + jglob0;
            const float* pB = gi + ((size_t)bbB*steps + np)*G3 + jglob0;
            grA = *(const float2*)(pA); gzA = *(const float2*)(pA+256); gnA = *(const float2*)(pA+512);
            grB = *(const float2*)(pB); gzB = *(const float2*)(pB+256); gnB = *(const float2*)(pB+512);
        }
        cluster_wait_();
    }
}

// ---------------- 4) attention + read + tanh(q*read) -> split-bf16 A' ----------------
__global__ void attn_kernel(){
    int b = blockIdx.x, h = threadIdx.x;
    __shared__ float en[S_];
    __shared__ float red[8];
    float qh = g_q[(size_t)b*H_ + h];
    int lane = h & 31, wid = h >> 5;
    for (int s = 0; s < S_; s++){
        float f = g_outf[((size_t)b*S_ + s)*H_ + h] + g_outb[((size_t)b*S_ + s)*H_ + h];
        float p = f * qh;
#pragma unroll
        for (int o = 16; o; o >>= 1) p += __shfl_xor_sync(0xffffffffu, p, o);
        if (lane == 0) red[wid] = p;
        __syncthreads();
        if (h < 8){
            float t = red[h];
            t += __shfl_xor_sync(0xffu, t, 4);
            t += __shfl_xor_sync(0xffu, t, 2);
            t += __shfl_xor_sync(0xffu, t, 1);
            if (h == 0) en[s] = t;
        }
        __syncthreads();
    }
    float mx = -1e30f;
    for (int s = 0; s < S_; s++) mx = fmaxf(mx, en[s]);
    float sum = 0.f;
    for (int s = 0; s < S_; s++) sum += expf(en[s] - mx);
    float inv = 1.f / sum;
    float rd = 0.f;
    for (int s = 0; s < S_; s++){
        float a = expf(en[s] - mx) * inv;
        rd += a * (g_outf[((size_t)b*S_ + s)*H_ + h] + g_outb[((size_t)b*S_ + s)*H_ + h]);
    }
    float v = tanhf(qh * rd);
    bf16 hi, lo; split_bf16_(v, hi, lo);
    bf16* dst = g_afA + (size_t)b*KTOT;
    dst[h] = hi; dst[h + 256] = hi; dst[h + 512] = lo;
}

// ---------------- launch ----------------
extern "C" void kernel_launch(void* const* d_in, const int* in_sizes, int n_in,
                              void* d_out, int out_size)
{
    const int*   contexts  = (const int*)  d_in[0];
    const int*   questions = (const int*)  d_in[1];
    const float* emb       = (const float*)d_in[2];
    const float* Wih_f     = (const float*)d_in[3];
    const float* Whh_f     = (const float*)d_in[4];
    const float* bih_f     = (const float*)d_in[5];
    const float* bhh_f     = (const float*)d_in[6];
    const float* Wih_b     = (const float*)d_in[7];
    const float* Whh_b     = (const float*)d_in[8];
    const float* bih_b     = (const float*)d_in[9];
    const float* bhh_b     = (const float*)d_in[10];
    const float* Wih_q     = (const float*)d_in[11];
    const float* Whh_q     = (const float*)d_in[12];
    const float* bih_q     = (const float*)d_in[13];
    const float* bhh_q     = (const float*)d_in[14];
    const float* Wo        = (const float*)d_in[15];
    const float* bo        = (const float*)d_in[16];
    float* out = (float*)d_out;

    cudaFuncSetAttribute(gru_kernel, cudaFuncAttributeMaxDynamicSharedMemorySize, GRU_SMEM_BYTES);

    // weight splits (independent of activations)
    convW3_kernel<<<dim3(G3, 3), 256>>>(Wih_f, Wih_b, Wih_q);
    convWo_kernel<<<VPAD, 256>>>(Wo);

    // 1) embeddings (fused split-bf16 write)
    embed_pe_kernel<<<B_*S_, 256>>>(contexts, emb);
    qemb_kernel<<<B_*TQ_, 256>>>(questions, emb);

    // 2) input-gate GEMMs on tensor cores
    bgemm3_kernel<<<dim3(B_*S_/128, G3/64, 3), 256>>>(bih_f, bih_b, bih_q);

    // 3) GRU chains on tensor cores (24 clusters x 4 CTAs)
    gru_kernel<<<96, 256, GRU_SMEM_BYTES>>>(Whh_f, Whh_b, Whh_q, bhh_f, bhh_b, bhh_q);

    // 4) attention + read + tanh (fused split-bf16 write)
    attn_kernel<<<B_, 256>>>();

    // 5) vocab projection on tensor cores
    bgemm_vocab_kernel<<<dim3(1, VPAD/64), 256>>>(bo, out);
}

// round 9
// speedup vs baseline: 3.5437x; 1.1766x over previous
#include <cuda_runtime.h>
#include <cuda_bf16.h>
#include <cstdint>
#include <cstdio>

#define B_  128
#define S_  50
#define T_  32
#define TQ_ 32
#define H_  256
#define V_  50257
#define G3  768
#define KTOT 768
#define VPAD 50304

typedef unsigned long long ull;
typedef __nv_bfloat16 bf16;

// ---------------- scratch (device globals; no allocation) ----------------
__device__ bf16  g_ctxA[B_*S_*KTOT];
__device__ bf16  g_qA  [B_*TQ_*KTOT];
__device__ bf16  g_afA [B_*KTOT];
__device__ bf16  g_wfA [G3*KTOT];
__device__ bf16  g_wbA [G3*KTOT];
__device__ bf16  g_wqA [G3*KTOT];
__device__ bf16  g_woA [VPAD*KTOT];
__device__ float g_gif [B_*S_*G3];
__device__ float g_gib [B_*S_*G3];
__device__ float g_giq [B_*TQ_*G3];
__device__ float g_outf[B_*S_*H_];
__device__ float g_outb[B_*S_*H_];
__device__ float g_q   [B_*H_];

// ---------------- helpers ----------------
__device__ __forceinline__ float sigmoidf_(float x){ return 1.0f/(1.0f+expf(-x)); }

__device__ __forceinline__ void split_bf16_(float v, bf16& hi, bf16& lo){
    hi = __float2bfloat16(v);
    lo = __float2bfloat16(v - __bfloat162float(hi));
}
__device__ __forceinline__ unsigned pack_bf2_(bf16 a, bf16 b){
    unsigned short x = *reinterpret_cast<unsigned short*>(&a);
    unsigned short y = *reinterpret_cast<unsigned short*>(&b);
    return (unsigned)x | ((unsigned)y << 16);
}
__device__ __forceinline__ unsigned smem_u32_(const void* p){
    unsigned r;
    asm("{ .reg .u64 t; cvta.to.shared.u64 t, %1; cvt.u32.u64 %0, t; }" : "=r"(r) : "l"(p));
    return r;
}
__device__ __forceinline__ unsigned mapa_(unsigned laddr, unsigned rank){
    unsigned r;
    asm("mapa.shared::cluster.u32 %0, %1, %2;" : "=r"(r) : "r"(laddr), "r"(rank));
    return r;
}
__device__ __forceinline__ void st_cluster_u32_(unsigned addr, unsigned v){
    asm volatile("st.shared::cluster.u32 [%0], %1;" :: "r"(addr), "r"(v) : "memory");
}
__device__ __forceinline__ void cluster_arrive_(){
    asm volatile("barrier.cluster.arrive.aligned;" ::: "memory");
}
__device__ __forceinline__ void cluster_wait_(){
    asm volatile("barrier.cluster.wait.aligned;" ::: "memory");
}
__device__ __forceinline__ unsigned ctarank_(){
    unsigned r; asm("mov.u32 %0, %%cluster_ctarank;" : "=r"(r)); return r;
}
__device__ __forceinline__ void mma_bf16_(float4& d, const unsigned a[4], const unsigned b[2]){
    asm("mma.sync.aligned.m16n8k16.row.col.f32.bf16.bf16.f32 "
        "{%0,%1,%2,%3}, {%4,%5,%6,%7}, {%8,%9}, {%0,%1,%2,%3};"
        : "+f"(d.x), "+f"(d.y), "+f"(d.z), "+f"(d.w)
        : "r"(a[0]), "r"(a[1]), "r"(a[2]), "r"(a[3]), "r"(b[0]), "r"(b[1]));
}
__device__ __forceinline__ void ldsm_x4_(unsigned af[4], unsigned addr){
    asm volatile("ldmatrix.sync.aligned.m8n8.x4.shared.b16 {%0,%1,%2,%3}, [%4];"
        : "=r"(af[0]), "=r"(af[1]), "=r"(af[2]), "=r"(af[3]) : "r"(addr));
}

// ---------------- 1) embedding + position encoding -> split-bf16 A' ----------------
__global__ void embed_pe_kernel(const int* __restrict__ ctx, const float* __restrict__ emb){
    int bs = blockIdx.x;
    int h  = threadIdx.x;
    __shared__ int ids[T_];
    if (h < T_) ids[h] = ctx[bs*T_ + h];
    __syncthreads();
    float e = (float)h * (1.0f/255.0f);
    float acc = 0.f;
#pragma unroll
    for (int t = 0; t < T_; t++){
        float s = (float)t * (1.0f/31.0f);
        float l = 1.0f - s - e*(1.0f - 2.0f*s);
        acc += emb[(size_t)ids[t]*H_ + h] * l;
    }
    bf16 hi, lo; split_bf16_(acc, hi, lo);
    bf16* dst = g_ctxA + (size_t)bs*KTOT;
    dst[h] = hi; dst[h + 256] = hi; dst[h + 512] = lo;
}

__global__ void qemb_kernel(const int* __restrict__ q, const float* __restrict__ emb){
    int i = blockIdx.x;
    int h = threadIdx.x;
    float v = emb[(size_t)q[i]*H_ + h];
    bf16 hi, lo; split_bf16_(v, hi, lo);
    bf16* dst = g_qA + (size_t)i*KTOT;
    dst[h] = hi; dst[h + 256] = hi; dst[h + 512] = lo;
}

// ---------------- weight split kernels (feedforward) ----------------
__global__ void convW3_kernel(const float* __restrict__ Wf, const float* __restrict__ Wb,
                              const float* __restrict__ Wq){
    int n = blockIdx.x;
    int k = threadIdx.x;
    const float* W; bf16* D;
    if (blockIdx.y == 0){ W = Wf; D = g_wfA; }
    else if (blockIdx.y == 1){ W = Wb; D = g_wbA; }
    else { W = Wq; D = g_wqA; }
    float v = W[(size_t)n*256 + k];
    bf16 hi, lo; split_bf16_(v, hi, lo);
    bf16* dst = D + (size_t)n*KTOT;
    dst[k] = hi; dst[k + 256] = lo; dst[k + 512] = hi;
}

__global__ void convWo_kernel(const float* __restrict__ Wo){
    int n = blockIdx.x;
    int k = threadIdx.x;
    float v = (n < V_) ? Wo[(size_t)n*256 + k] : 0.f;
    bf16 hi, lo; split_bf16_(v, hi, lo);
    bf16* dst = g_woA + (size_t)n*KTOT;
    dst[k] = hi; dst[k + 256] = lo; dst[k + 512] = hi;
}

// ---------------- 2) split-bf16 tensor GEMM (passing version) ----------------
#define AST 72
__device__ __forceinline__ void bgemm_body(const bf16* __restrict__ A,
                                           const bf16* __restrict__ W,
                                           const float* __restrict__ bias,
                                           float* __restrict__ C,
                                           int Nv, int bm, int bn)
{
    __shared__ bf16 As[128*AST];
    __shared__ bf16 Bs[64*AST];
    int tid = threadIdx.x;
    int lane = tid & 31, wid = tid >> 5;
    int wm = (wid & 3) * 32;
    int wn = (wid >> 2) * 32;

    float4 acc[2][4];
#pragma unroll
    for (int i = 0; i < 2; i++)
#pragma unroll
        for (int j = 0; j < 4; j++) acc[i][j] = make_float4(0.f,0.f,0.f,0.f);

    for (int k0 = 0; k0 < KTOT; k0 += 64){
#pragma unroll
        for (int i = 0; i < 4; i++){
            int idx = tid + i*256;
            int r = idx >> 3, ck = idx & 7;
            uint4 v = *(const uint4*)(A + (size_t)(bm + r)*KTOT + k0 + ck*8);
            *(uint4*)(As + r*AST + ck*8) = v;
        }
#pragma unroll
        for (int i = 0; i < 2; i++){
            int idx = tid + i*256;
            int r = idx >> 3, ck = idx & 7;
            uint4 v = *(const uint4*)(W + (size_t)(bn + r)*KTOT + k0 + ck*8);
            *(uint4*)(Bs + r*AST + ck*8) = v;
        }
        __syncthreads();
        int r = lane >> 2, c2 = (lane & 3) * 2;
#pragma unroll
        for (int kk = 0; kk < 4; kk++){
            unsigned af[2][4], bfr[4][2];
#pragma unroll
            for (int i = 0; i < 2; i++){
                const bf16* ab = As + (wm + i*16)*AST + kk*16;
                af[i][0] = *(const unsigned*)(ab + (r    )*AST + c2    );
                af[i][1] = *(const unsigned*)(ab + (r + 8)*AST + c2    );
                af[i][2] = *(const unsigned*)(ab + (r    )*AST + c2 + 8);
                af[i][3] = *(const unsigned*)(ab + (r + 8)*AST + c2 + 8);
            }
#pragma unroll
            for (int j = 0; j < 4; j++){
                const bf16* bb = Bs + (wn + j*8)*AST + kk*16;
                bfr[j][0] = *(const unsigned*)(bb + r*AST + c2    );
                bfr[j][1] = *(const unsigned*)(bb + r*AST + c2 + 8);
            }
#pragma unroll
            for (int i = 0; i < 2; i++)
#pragma unroll
                for (int j = 0; j < 4; j++)
                    mma_bf16_(acc[i][j], af[i], bfr[j]);
        }
        __syncthreads();
    }
    int r = lane >> 2, c2 = (lane & 3) * 2;
    bool even_stride = ((Nv & 1) == 0);
#pragma unroll
    for (int i = 0; i < 2; i++){
        int m0 = bm + wm + i*16 + r;
#pragma unroll
        for (int j = 0; j < 4; j++){
            int n0 = bn + wn + j*8 + c2;
            if (n0 < Nv){
                float4 a = acc[i][j];
                float b0 = bias[n0];
                if (n0 + 1 < Nv){
                    float b1 = bias[n0+1];
                    if (even_stride){
                        *(float2*)(C + (size_t)m0*Nv + n0)     = make_float2(a.x + b0, a.y + b1);
                        *(float2*)(C + (size_t)(m0+8)*Nv + n0) = make_float2(a.z + b0, a.w + b1);
                    } else {
                        C[(size_t)m0*Nv + n0]         = a.x + b0;
                        C[(size_t)m0*Nv + n0 + 1]     = a.y + b1;
                        C[(size_t)(m0+8)*Nv + n0]     = a.z + b0;
                        C[(size_t)(m0+8)*Nv + n0 + 1] = a.w + b1;
                    }
                } else {
                    C[(size_t)m0*Nv + n0]     = a.x + b0;
                    C[(size_t)(m0+8)*Nv + n0] = a.z + b0;
                }
            }
        }
    }
}

__global__ __launch_bounds__(256) void bgemm3_kernel(
    const float* bias_f, const float* bias_b, const float* bias_q)
{
    const bf16 *A, *W; const float* bias; float* C; int M;
    if (blockIdx.z == 0){ A = g_ctxA; W = g_wfA; bias = bias_f; C = g_gif; M = B_*S_; }
    else if (blockIdx.z == 1){ A = g_ctxA; W = g_wbA; bias = bias_b; C = g_gib; M = B_*S_; }
    else { A = g_qA; W = g_wqA; bias = bias_q; C = g_giq; M = B_*TQ_; }
    int bm = blockIdx.x * 128;
    if (bm >= M) return;
    bgemm_body(A, W, bias, C, G3, bm, blockIdx.y * 64);
}

__global__ __launch_bounds__(256) void bgemm_vocab_kernel(const float* __restrict__ bo,
                                                          float* __restrict__ out)
{
    bgemm_body(g_afA, g_woA, bo, out, V_, 0, blockIdx.y * 64);
}

// ---------------- 3) GRU on tensor cores: W fragments register-resident ----------------
// Cluster of 4 CTAs, 16 batches/cluster, CTA owns 64 j (192 gate rows).
// 256 threads (8 warps; warp = 8-j block -> 3 gate n-tiles).
// W split-staged in smem ONCE, fragments preloaded to 192 regs/thread, smem W dead after.
// hbuf double-buffered (buf1 aliases dead Whi region) -> ONE barrier round per step.
#define GRU_WST 264
#define GRU_HST 520
#define GRU_WPLANE (192*GRU_WST)
#define GRU_SMEM_BF16 (2*GRU_WPLANE + 16*GRU_HST)
#define GRU_SMEM_BYTES (GRU_SMEM_BF16*2)

__global__ void __cluster_dims__(4,1,1) __launch_bounds__(256,1)
gru_kernel(const float* __restrict__ Whh_f, const float* __restrict__ Whh_b, const float* __restrict__ Whh_q,
           const float* __restrict__ bhh_f, const float* __restrict__ bhh_b, const float* __restrict__ bhh_q)
{
    extern __shared__ bf16 smb[];
    bf16* Whi   = smb;                    // [192][264] (dead after preload)
    bf16* Wlo   = smb + GRU_WPLANE;       // [192][264]
    bf16* hbuf0 = smb + 2*GRU_WPLANE;     // [16][520]: k 0-255 hi, 256-511 lo
    bf16* hbuf1 = smb;                    // aliases Whi region

    int tid  = threadIdx.x;
    int lane = tid & 31, w = tid >> 5;
    unsigned rank = ctarank_();
    int cid   = blockIdx.x >> 2;
    int chain = cid >> 3;
    int b0    = (cid & 7) * 16;

    const float *Whh, *bhh, *gi;
    float* outp;
    int steps;
    if (chain == 0){ Whh = Whh_f; bhh = bhh_f; gi = g_gif; outp = g_outf; steps = S_;  }
    else if (chain == 1){ Whh = Whh_b; bhh = bhh_b; gi = g_gib; outp = g_outb; steps = S_;  }
    else { Whh = Whh_q; bhh = bhh_q; gi = g_giq; outp = g_q;    steps = TQ_; }

    // ---- stage + split Whh slice into smem; zero hbuf0
    {
#pragma unroll 4
        for (int rr = 0; rr < 192; rr++){
            int grow = (rr >> 6)*256 + (int)rank*64 + (rr & 63);
            float v = Whh[(size_t)grow*256 + tid];
            bf16 hi, lo; split_bf16_(v, hi, lo);
            Whi[rr*GRU_WST + tid] = hi;
            Wlo[rr*GRU_WST + tid] = lo;
        }
        unsigned* hz = (unsigned*)hbuf0;
        for (int i = tid; i < 16*GRU_HST/2; i += 256) hz[i] = 0u;
    }
    __syncthreads();

    // ---- fragment geometry
    int r  = lane >> 2;
    int c2 = (lane & 3) * 2;
    int jglob0 = (int)rank*64 + w*8 + c2;

    // ---- preload W fragments to registers: Bf[kt][gate][plane][reg]
    unsigned Bf[16][3][2][2];
#pragma unroll
    for (int kt = 0; kt < 16; kt++){
#pragma unroll
        for (int g = 0; g < 3; g++){
            const bf16* ph = Whi + (g*64 + w*8 + r)*GRU_WST + kt*16 + c2;
            const bf16* pl = Wlo + (g*64 + w*8 + r)*GRU_WST + kt*16 + c2;
            Bf[kt][g][0][0] = *(const unsigned*)(ph);
            Bf[kt][g][0][1] = *(const unsigned*)(ph + 8);
            Bf[kt][g][1][0] = *(const unsigned*)(pl);
            Bf[kt][g][1][1] = *(const unsigned*)(pl + 8);
        }
    }

    // ---- LDSM A-operand addresses (lane -> row lane&15, k-half (lane>>4)*8)
    unsigned hb0 = smem_u32_(hbuf0), hb1 = smem_u32_(hbuf1);
    unsigned arow = (unsigned)((lane & 15)*GRU_HST*2 + ((lane >> 4) << 3)*2);

    int bbA = b0 + r, bbB = b0 + r + 8;
    float hpA0 = 0.f, hpA1 = 0.f, hpB0 = 0.f, hpB1 = 0.f;

    // all CTAs done staging+preloading before anyone writes hbuf1 (aliases Whi)
    cluster_arrive_();
    cluster_wait_();

    for (int step = 0; step < steps; step++){
        int pos = (chain == 1) ? (S_ - 1 - step) : step;
        unsigned rb = (step & 1) ? hb1 : hb0;   // read buffer
        unsigned wb = (step & 1) ? hb0 : hb1;   // write buffer (next)
        unsigned abase = rb + arow;

        float4 accR = make_float4(0.f,0.f,0.f,0.f);
        float4 accZ = make_float4(0.f,0.f,0.f,0.f);
        float4 accN = make_float4(0.f,0.f,0.f,0.f);

        // pass 1: A = h_hi, B = W_hi then W_lo (registers)
#pragma unroll
        for (int kt = 0; kt < 16; kt++){
            unsigned af[4];
            ldsm_x4_(af, abase + kt*32);
            mma_bf16_(accR, af, Bf[kt][0][0]);
            mma_bf16_(accZ, af, Bf[kt][1][0]);
            mma_bf16_(accN, af, Bf[kt][2][0]);
            mma_bf16_(accR, af, Bf[kt][0][1]);
            mma_bf16_(accZ, af, Bf[kt][1][1]);
            mma_bf16_(accN, af, Bf[kt][2][1]);
        }

        // gi loads issue here; latency hidden under pass 2
        float2 grA, gzA, gnA, grB, gzB, gnB;
        {
            const float* pA = gi + ((size_t)bbA*steps + pos)*G3 + jglob0;
            const float* pB = gi + ((size_t)bbB*steps + pos)*G3 + jglob0;
            grA = *(const float2*)(pA); gzA = *(const float2*)(pA+256); gnA = *(const float2*)(pA+512);
            grB = *(const float2*)(pB); gzB = *(const float2*)(pB+256); gnB = *(const float2*)(pB+512);
        }

        // pass 2: A = h_lo (k+512B), B = W_hi
#pragma unroll
        for (int kt = 0; kt < 16; kt++){
            unsigned af[4];
            ldsm_x4_(af, abase + 512 + kt*32);
            mma_bf16_(accR, af, Bf[kt][0][0]);
            mma_bf16_(accZ, af, Bf[kt][1][0]);
            mma_bf16_(accN, af, Bf[kt][2][0]);
        }

        // biases (L1-resident after step 0)
        float2 br2 = *(const float2*)(bhh       + jglob0);
        float2 bz2 = *(const float2*)(bhh + 256 + jglob0);
        float2 bn2 = *(const float2*)(bhh + 512 + jglob0);

        float rA0 = sigmoidf_(grA.x + accR.x + br2.x);
        float zA0 = sigmoidf_(gzA.x + accZ.x + bz2.x);
        float nA0 = tanhf   (gnA.x + rA0*(accN.x + bn2.x));
        float hA0 = (1.f - zA0)*nA0 + zA0*hpA0; hpA0 = hA0;
        float rA1 = sigmoidf_(grA.y + accR.y + br2.y);
        float zA1 = sigmoidf_(gzA.y + accZ.y + bz2.y);
        float nA1 = tanhf   (gnA.y + rA1*(accN.y + bn2.y));
        float hA1 = (1.f - zA1)*nA1 + zA1*hpA1; hpA1 = hA1;
        float rB0 = sigmoidf_(grB.x + accR.z + br2.x);
        float zB0 = sigmoidf_(gzB.x + accZ.z + bz2.x);
        float nB0 = tanhf   (gnB.x + rB0*(accN.z + bn2.x));
        float hB0 = (1.f - zB0)*nB0 + zB0*hpB0; hpB0 = hB0;
        float rB1 = sigmoidf_(grB.y + accR.w + br2.y);
        float zB1 = sigmoidf_(gzB.y + accZ.w + bz2.y);
        float nB1 = tanhf   (gnB.y + rB1*(accN.w + bn2.y));
        float hB1 = (1.f - zB1)*nB1 + zB1*hpB1; hpB1 = hB1;

        bf16 hiA0, loA0, hiA1, loA1, hiB0, loB0, hiB1, loB1;
        split_bf16_(hA0, hiA0, loA0); split_bf16_(hA1, hiA1, loA1);
        split_bf16_(hB0, hiB0, loB0); split_bf16_(hB1, hiB1, loB1);
        unsigned uAhi = pack_bf2_(hiA0, hiA1), uAlo = pack_bf2_(loA0, loA1);
        unsigned uBhi = pack_bf2_(hiB0, hiB1), uBlo = pack_bf2_(loB0, loB1);

        // write NEXT buffer on all 4 CTAs (read buffer untouched -> no mid-step barrier)
        {
            unsigned offAhi = (unsigned)((r*GRU_HST + jglob0)*2);
            unsigned offAlo = offAhi + 512;
            unsigned offBhi = (unsigned)(((r+8)*GRU_HST + jglob0)*2);
            unsigned offBlo = offBhi + 512;
            unsigned p0 = mapa_(wb, 0), p1 = mapa_(wb, 1), p2 = mapa_(wb, 2), p3 = mapa_(wb, 3);
            st_cluster_u32_(p0 + offAhi, uAhi); st_cluster_u32_(p0 + offAlo, uAlo);
            st_cluster_u32_(p0 + offBhi, uBhi); st_cluster_u32_(p0 + offBlo, uBlo);
            st_cluster_u32_(p1 + offAhi, uAhi); st_cluster_u32_(p1 + offAlo, uAlo);
            st_cluster_u32_(p1 + offBhi, uBhi); st_cluster_u32_(p1 + offBlo, uBlo);
            st_cluster_u32_(p2 + offAhi, uAhi); st_cluster_u32_(p2 + offAlo, uAlo);
            st_cluster_u32_(p2 + offBhi, uBhi); st_cluster_u32_(p2 + offBlo, uBlo);
            st_cluster_u32_(p3 + offAhi, uAhi); st_cluster_u32_(p3 + offAlo, uAlo);
            st_cluster_u32_(p3 + offBhi, uBhi); st_cluster_u32_(p3 + offBlo, uBlo);
        }
        cluster_arrive_();

        // global outputs overlap the barrier
        if (chain == 2){
            if (step == steps - 1){
                *(float2*)(outp + (size_t)bbA*H_ + jglob0) = make_float2(hA0, hA1);
                *(float2*)(outp + (size_t)bbB*H_ + jglob0) = make_float2(hB0, hB1);
            }
        } else {
            *(float2*)(outp + ((size_t)bbA*S_ + pos)*H_ + jglob0) = make_float2(hA0, hA1);
            *(float2*)(outp + ((size_t)bbB*S_ + pos)*H_ + jglob0) = make_float2(hB0, hB1);
        }
        cluster_wait_();
    }
}

// ---------------- 4) attention + read + tanh(q*read) -> split-bf16 A' ----------------
__global__ void attn_kernel(){
    int b = blockIdx.x, h = threadIdx.x;
    __shared__ float en[S_];
    __shared__ float red[8];
    float qh = g_q[(size_t)b*H_ + h];
    int lane = h & 31, wid = h >> 5;
    for (int s = 0; s < S_; s++){
        float f = g_outf[((size_t)b*S_ + s)*H_ + h] + g_outb[((size_t)b*S_ + s)*H_ + h];
        float p = f * qh;
#pragma unroll
        for (int o = 16; o; o >>= 1) p += __shfl_xor_sync(0xffffffffu, p, o);
        if (lane == 0) red[wid] = p;
        __syncthreads();
        if (h < 8){
            float t = red[h];
            t += __shfl_xor_sync(0xffu, t, 4);
            t += __shfl_xor_sync(0xffu, t, 2);
            t += __shfl_xor_sync(0xffu, t, 1);
            if (h == 0) en[s] = t;
        }
        __syncthreads();
    }
    float mx = -1e30f;
    for (int s = 0; s < S_; s++) mx = fmaxf(mx, en[s]);
    float sum = 0.f;
    for (int s = 0; s < S_; s++) sum += expf(en[s] - mx);
    float inv = 1.f / sum;
    float rd = 0.f;
    for (int s = 0; s < S_; s++){
        float a = expf(en[s] - mx) * inv;
        rd += a * (g_outf[((size_t)b*S_ + s)*H_ + h] + g_outb[((size_t)b*S_ + s)*H_ + h]);
    }
    float v = tanhf(qh * rd);
    bf16 hi, lo; split_bf16_(v, hi, lo);
    bf16* dst = g_afA + (size_t)b*KTOT;
    dst[h] = hi; dst[h + 256] = hi; dst[h + 512] = lo;
}

// ---------------- launch ----------------
extern "C" void kernel_launch(void* const* d_in, const int* in_sizes, int n_in,
                              void* d_out, int out_size)
{
    const int*   contexts  = (const int*)  d_in[0];
    const int*   questions = (const int*)  d_in[1];
    const float* emb       = (const float*)d_in[2];
    const float* Wih_f     = (const float*)d_in[3];
    const float* Whh_f     = (const float*)d_in[4];
    const float* bih_f     = (const float*)d_in[5];
    const float* bhh_f     = (const float*)d_in[6];
    const float* Wih_b     = (const float*)d_in[7];
    const float* Whh_b     = (const float*)d_in[8];
    const float* bih_b     = (const float*)d_in[9];
    const float* bhh_b     = (const float*)d_in[10];
    const float* Wih_q     = (const float*)d_in[11];
    const float* Whh_q     = (const float*)d_in[12];
    const float* bih_q     = (const float*)d_in[13];
    const float* bhh_q     = (const float*)d_in[14];
    const float* Wo        = (const float*)d_in[15];
    const float* bo        = (const float*)d_in[16];
    float* out = (float*)d_out;

    cudaFuncSetAttribute(gru_kernel, cudaFuncAttributeMaxDynamicSharedMemorySize, GRU_SMEM_BYTES);

    // weight splits (independent of activations)
    convW3_kernel<<<dim3(G3, 3), 256>>>(Wih_f, Wih_b, Wih_q);
    convWo_kernel<<<VPAD, 256>>>(Wo);

    // 1) embeddings (fused split-bf16 write)
    embed_pe_kernel<<<B_*S_, 256>>>(contexts, emb);
    qemb_kernel<<<B_*TQ_, 256>>>(questions, emb);

    // 2) input-gate GEMMs on tensor cores
    bgemm3_kernel<<<dim3(B_*S_/128, G3/64, 3), 256>>>(bih_f, bih_b, bih_q);

    // 3) GRU chains on tensor cores (24 clusters x 4 CTAs)
    gru_kernel<<<96, 256, GRU_SMEM_BYTES>>>(Whh_f, Whh_b, Whh_q, bhh_f, bhh_b, bhh_q);

    // 4) attention + read + tanh (fused split-bf16 write)
    attn_kernel<<<B_, 256>>>();

    // 5) vocab projection on tensor cores
    bgemm_vocab_kernel<<<dim3(1, VPAD/64), 256>>>(bo, out);
}

// round 10
// speedup vs baseline: 3.8781x; 1.0944x over previous
#include <cuda_runtime.h>
#include <cuda_bf16.h>
#include <cstdint>
#include <cstdio>

#define B_  128
#define S_  50
#define T_  32
#define TQ_ 32
#define H_  256
#define V_  50257
#define G3  768
#define KTOT 768
#define VPAD 50304

typedef unsigned long long ull;
typedef __nv_bfloat16 bf16;

// ---------------- scratch (device globals; no allocation) ----------------
__device__ bf16  g_ctxA[B_*S_*KTOT];
__device__ bf16  g_qA  [B_*TQ_*KTOT];
__device__ bf16  g_afA [B_*KTOT];
__device__ bf16  g_wfA [G3*KTOT];
__device__ bf16  g_wbA [G3*KTOT];
__device__ bf16  g_wqA [G3*KTOT];
__device__ bf16  g_woA [VPAD*KTOT];
__device__ float g_gif [B_*S_*G3];
__device__ float g_gib [B_*S_*G3];
__device__ float g_giq [B_*TQ_*G3];
__device__ float g_outf[B_*S_*H_];
__device__ float g_outb[B_*S_*H_];
__device__ float g_q   [B_*H_];

// ---------------- helpers ----------------
__device__ __forceinline__ float fexp_(float x){
    float y;
    asm("ex2.approx.ftz.f32 %0, %1;" : "=f"(y) : "f"(x * 1.4426950408889634f));
    return y;
}
__device__ __forceinline__ float frcp_(float x){
    float y; asm("rcp.approx.ftz.f32 %0, %1;" : "=f"(y) : "f"(x)); return y;
}
__device__ __forceinline__ float fsig_(float x){   // 1/(1+e^-x), err ~1e-6
    return frcp_(1.f + fexp_(-x));
}
__device__ __forceinline__ float ftanh_(float x){  // 2*sigmoid(2x)-1, err ~1e-6
    return 2.f*frcp_(1.f + fexp_(-2.f*x)) - 1.f;
}
__device__ __forceinline__ void split_bf16_(float v, bf16& hi, bf16& lo){
    hi = __float2bfloat16(v);
    lo = __float2bfloat16(v - __bfloat162float(hi));
}
__device__ __forceinline__ unsigned pack_bf2_(bf16 a, bf16 b){
    unsigned short x = *reinterpret_cast<unsigned short*>(&a);
    unsigned short y = *reinterpret_cast<unsigned short*>(&b);
    return (unsigned)x | ((unsigned)y << 16);
}
__device__ __forceinline__ unsigned smem_u32_(const void* p){
    unsigned r;
    asm("{ .reg .u64 t; cvta.to.shared.u64 t, %1; cvt.u32.u64 %0, t; }" : "=r"(r) : "l"(p));
    return r;
}
__device__ __forceinline__ unsigned mapa_(unsigned laddr, unsigned rank){
    unsigned r;
    asm("mapa.shared::cluster.u32 %0, %1, %2;" : "=r"(r) : "r"(laddr), "r"(rank));
    return r;
}
__device__ __forceinline__ void st_cluster_u32_(unsigned addr, unsigned v){
    asm volatile("st.shared::cluster.u32 [%0], %1;" :: "r"(addr), "r"(v) : "memory");
}
__device__ __forceinline__ void cluster_arrive_(){
    asm volatile("barrier.cluster.arrive.aligned;" ::: "memory");
}
__device__ __forceinline__ void cluster_wait_(){
    asm volatile("barrier.cluster.wait.aligned;" ::: "memory");
}
__device__ __forceinline__ unsigned ctarank_(){
    unsigned r; asm("mov.u32 %0, %%cluster_ctarank;" : "=r"(r)); return r;
}
__device__ __forceinline__ void mma_bf16_(float4& d, const unsigned a[4], const unsigned b[2]){
    asm("mma.sync.aligned.m16n8k16.row.col.f32.bf16.bf16.f32 "
        "{%0,%1,%2,%3}, {%4,%5,%6,%7}, {%8,%9}, {%0,%1,%2,%3};"
        : "+f"(d.x), "+f"(d.y), "+f"(d.z), "+f"(d.w)
        : "r"(a[0]), "r"(a[1]), "r"(a[2]), "r"(a[3]), "r"(b[0]), "r"(b[1]));
}
__device__ __forceinline__ void ldsm_x4_(unsigned af[4], unsigned addr){
    asm volatile("ldmatrix.sync.aligned.m8n8.x4.shared.b16 {%0,%1,%2,%3}, [%4];"
        : "=r"(af[0]), "=r"(af[1]), "=r"(af[2]), "=r"(af[3]) : "r"(addr));
}

// ---------------- 1) fused prep: embed_pe | qemb | convW3 | convWo ----------------
#define PREP_EMB   (B_*S_)                 // 6400
#define PREP_QEMB  (PREP_EMB + B_*TQ_)     // +4096
#define PREP_W3    (PREP_QEMB + 3*G3)      // +2304
#define PREP_TOTAL (PREP_W3 + VPAD)        // +50304 = 63104

__global__ __launch_bounds__(256) void prep_kernel(
    const int* __restrict__ ctx, const int* __restrict__ q, const float* __restrict__ emb,
    const float* __restrict__ Wf, const float* __restrict__ Wb, const float* __restrict__ Wq,
    const float* __restrict__ Wo)
{
    int bid = blockIdx.x;
    int h   = threadIdx.x;
    if (bid < PREP_EMB){
        // embedding + position encoding -> split-bf16 A'
        int bs = bid;
        __shared__ int ids[T_];
        if (h < T_) ids[h] = ctx[bs*T_ + h];
        __syncthreads();
        float e = (float)h * (1.0f/255.0f);
        float acc = 0.f;
#pragma unroll
        for (int t = 0; t < T_; t++){
            float s = (float)t * (1.0f/31.0f);
            float l = 1.0f - s - e*(1.0f - 2.0f*s);
            acc += emb[(size_t)ids[t]*H_ + h] * l;
        }
        bf16 hi, lo; split_bf16_(acc, hi, lo);
        bf16* dst = g_ctxA + (size_t)bs*KTOT;
        dst[h] = hi; dst[h + 256] = hi; dst[h + 512] = lo;
    } else if (bid < PREP_QEMB){
        int i = bid - PREP_EMB;
        float v = emb[(size_t)q[i]*H_ + h];
        bf16 hi, lo; split_bf16_(v, hi, lo);
        bf16* dst = g_qA + (size_t)i*KTOT;
        dst[h] = hi; dst[h + 256] = hi; dst[h + 512] = lo;
    } else if (bid < PREP_W3){
        int idx = bid - PREP_QEMB;
        int sel = idx / G3, n = idx % G3;
        const float* W; bf16* D;
        if (sel == 0){ W = Wf; D = g_wfA; }
        else if (sel == 1){ W = Wb; D = g_wbA; }
        else { W = Wq; D = g_wqA; }
        float v = W[(size_t)n*256 + h];
        bf16 hi, lo; split_bf16_(v, hi, lo);
        bf16* dst = D + (size_t)n*KTOT;
        dst[h] = hi; dst[h + 256] = lo; dst[h + 512] = hi;
    } else {
        int n = bid - PREP_W3;   // 0..VPAD-1
        float v = (n < V_) ? Wo[(size_t)n*256 + h] : 0.f;
        bf16 hi, lo; split_bf16_(v, hi, lo);
        bf16* dst = g_woA + (size_t)n*KTOT;
        dst[h] = hi; dst[h + 256] = lo; dst[h + 512] = hi;
    }
}

// ---------------- 2) split-bf16 tensor GEMM (passing version) ----------------
#define AST 72
__device__ __forceinline__ void bgemm_body(const bf16* __restrict__ A,
                                           const bf16* __restrict__ W,
                                           const float* __restrict__ bias,
                                           float* __restrict__ C,
                                           int Nv, int bm, int bn)
{
    __shared__ bf16 As[128*AST];
    __shared__ bf16 Bs[64*AST];
    int tid = threadIdx.x;
    int lane = tid & 31, wid = tid >> 5;
    int wm = (wid & 3) * 32;
    int wn = (wid >> 2) * 32;

    float4 acc[2][4];
#pragma unroll
    for (int i = 0; i < 2; i++)
#pragma unroll
        for (int j = 0; j < 4; j++) acc[i][j] = make_float4(0.f,0.f,0.f,0.f);

    for (int k0 = 0; k0 < KTOT; k0 += 64){
#pragma unroll
        for (int i = 0; i < 4; i++){
            int idx = tid + i*256;
            int r = idx >> 3, ck = idx & 7;
            uint4 v = *(const uint4*)(A + (size_t)(bm + r)*KTOT + k0 + ck*8);
            *(uint4*)(As + r*AST + ck*8) = v;
        }
#pragma unroll
        for (int i = 0; i < 2; i++){
            int idx = tid + i*256;
            int r = idx >> 3, ck = idx & 7;
            uint4 v = *(const uint4*)(W + (size_t)(bn + r)*KTOT + k0 + ck*8);
            *(uint4*)(Bs + r*AST + ck*8) = v;
        }
        __syncthreads();
        int r = lane >> 2, c2 = (lane & 3) * 2;
#pragma unroll
        for (int kk = 0; kk < 4; kk++){
            unsigned af[2][4], bfr[4][2];
#pragma unroll
            for (int i = 0; i < 2; i++){
                const bf16* ab = As + (wm + i*16)*AST + kk*16;
                af[i][0] = *(const unsigned*)(ab + (r    )*AST + c2    );
                af[i][1] = *(const unsigned*)(ab + (r + 8)*AST + c2    );
                af[i][2] = *(const unsigned*)(ab + (r    )*AST + c2 + 8);
                af[i][3] = *(const unsigned*)(ab + (r + 8)*AST + c2 + 8);
            }
#pragma unroll
            for (int j = 0; j < 4; j++){
                const bf16* bb = Bs + (wn + j*8)*AST + kk*16;
                bfr[j][0] = *(const unsigned*)(bb + r*AST + c2    );
                bfr[j][1] = *(const unsigned*)(bb + r*AST + c2 + 8);
            }
#pragma unroll
            for (int i = 0; i < 2; i++)
#pragma unroll
                for (int j = 0; j < 4; j++)
                    mma_bf16_(acc[i][j], af[i], bfr[j]);
        }
        __syncthreads();
    }
    int r = lane >> 2, c2 = (lane & 3) * 2;
    bool even_stride = ((Nv & 1) == 0);
#pragma unroll
    for (int i = 0; i < 2; i++){
        int m0 = bm + wm + i*16 + r;
#pragma unroll
        for (int j = 0; j < 4; j++){
            int n0 = bn + wn + j*8 + c2;
            if (n0 < Nv){
                float4 a = acc[i][j];
                float b0 = bias[n0];
                if (n0 + 1 < Nv){
                    float b1 = bias[n0+1];
                    if (even_stride){
                        *(float2*)(C + (size_t)m0*Nv + n0)     = make_float2(a.x + b0, a.y + b1);
                        *(float2*)(C + (size_t)(m0+8)*Nv + n0) = make_float2(a.z + b0, a.w + b1);
                    } else {
                        C[(size_t)m0*Nv + n0]         = a.x + b0;
                        C[(size_t)m0*Nv + n0 + 1]     = a.y + b1;
                        C[(size_t)(m0+8)*Nv + n0]     = a.z + b0;
                        C[(size_t)(m0+8)*Nv + n0 + 1] = a.w + b1;
                    }
                } else {
                    C[(size_t)m0*Nv + n0]     = a.x + b0;
                    C[(size_t)(m0+8)*Nv + n0] = a.z + b0;
                }
            }
        }
    }
}

__global__ __launch_bounds__(256) void bgemm3_kernel(
    const float* bias_f, const float* bias_b, const float* bias_q)
{
    const bf16 *A, *W; const float* bias; float* C; int M;
    if (blockIdx.z == 0){ A = g_ctxA; W = g_wfA; bias = bias_f; C = g_gif; M = B_*S_; }
    else if (blockIdx.z == 1){ A = g_ctxA; W = g_wbA; bias = bias_b; C = g_gib; M = B_*S_; }
    else { A = g_qA; W = g_wqA; bias = bias_q; C = g_giq; M = B_*TQ_; }
    int bm = blockIdx.x * 128;
    if (bm >= M) return;
    bgemm_body(A, W, bias, C, G3, bm, blockIdx.y * 64);
}

__global__ __launch_bounds__(256) void bgemm_vocab_kernel(const float* __restrict__ bo,
                                                          float* __restrict__ out)
{
    bgemm_body(g_afA, g_woA, bo, out, V_, 0, blockIdx.y * 64);
}

// ---------------- 3) GRU on tensor cores (R9 structure + fast transcendentals) ----------------
#define GRU_WST 264
#define GRU_HST 520
#define GRU_WPLANE (192*GRU_WST)
#define GRU_SMEM_BF16 (2*GRU_WPLANE + 16*GRU_HST)
#define GRU_SMEM_BYTES (GRU_SMEM_BF16*2)

__global__ void __cluster_dims__(4,1,1) __launch_bounds__(256,1)
gru_kernel(const float* __restrict__ Whh_f, const float* __restrict__ Whh_b, const float* __restrict__ Whh_q,
           const float* __restrict__ bhh_f, const float* __restrict__ bhh_b, const float* __restrict__ bhh_q)
{
    extern __shared__ bf16 smb[];
    bf16* Whi   = smb;                    // [192][264] (dead after preload)
    bf16* Wlo   = smb + GRU_WPLANE;       // [192][264]
    bf16* hbuf0 = smb + 2*GRU_WPLANE;     // [16][520]: k 0-255 hi, 256-511 lo
    bf16* hbuf1 = smb;                    // aliases Whi region

    int tid  = threadIdx.x;
    int lane = tid & 31, w = tid >> 5;
    unsigned rank = ctarank_();
    int cid   = blockIdx.x >> 2;
    int chain = cid >> 3;
    int b0    = (cid & 7) * 16;

    const float *Whh, *bhh, *gi;
    float* outp;
    int steps;
    if (chain == 0){ Whh = Whh_f; bhh = bhh_f; gi = g_gif; outp = g_outf; steps = S_;  }
    else if (chain == 1){ Whh = Whh_b; bhh = bhh_b; gi = g_gib; outp = g_outb; steps = S_;  }
    else { Whh = Whh_q; bhh = bhh_q; gi = g_giq; outp = g_q;    steps = TQ_; }

    // ---- stage + split Whh slice into smem; zero hbuf0
    {
#pragma unroll 4
        for (int rr = 0; rr < 192; rr++){
            int grow = (rr >> 6)*256 + (int)rank*64 + (rr & 63);
            float v = Whh[(size_t)grow*256 + tid];
            bf16 hi, lo; split_bf16_(v, hi, lo);
            Whi[rr*GRU_WST + tid] = hi;
            Wlo[rr*GRU_WST + tid] = lo;
        }
        unsigned* hz = (unsigned*)hbuf0;
        for (int i = tid; i < 16*GRU_HST/2; i += 256) hz[i] = 0u;
    }
    __syncthreads();

    // ---- fragment geometry
    int r  = lane >> 2;
    int c2 = (lane & 3) * 2;
    int jglob0 = (int)rank*64 + w*8 + c2;

    // ---- preload W fragments to registers: Bf[kt][gate][plane][reg]
    unsigned Bf[16][3][2][2];
#pragma unroll
    for (int kt = 0; kt < 16; kt++){
#pragma unroll
        for (int g = 0; g < 3; g++){
            const bf16* ph = Whi + (g*64 + w*8 + r)*GRU_WST + kt*16 + c2;
            const bf16* pl = Wlo + (g*64 + w*8 + r)*GRU_WST + kt*16 + c2;
            Bf[kt][g][0][0] = *(const unsigned*)(ph);
            Bf[kt][g][0][1] = *(const unsigned*)(ph + 8);
            Bf[kt][g][1][0] = *(const unsigned*)(pl);
            Bf[kt][g][1][1] = *(const unsigned*)(pl + 8);
        }
    }

    unsigned hb0 = smem_u32_(hbuf0), hb1 = smem_u32_(hbuf1);
    unsigned arow = (unsigned)((lane & 15)*GRU_HST*2 + ((lane >> 4) << 3)*2);

    int bbA = b0 + r, bbB = b0 + r + 8;
    float hpA0 = 0.f, hpA1 = 0.f, hpB0 = 0.f, hpB1 = 0.f;

    cluster_arrive_();
    cluster_wait_();

    for (int step = 0; step < steps; step++){
        int pos = (chain == 1) ? (S_ - 1 - step) : step;
        unsigned rb = (step & 1) ? hb1 : hb0;
        unsigned wb = (step & 1) ? hb0 : hb1;
        unsigned abase = rb + arow;

        float4 accR = make_float4(0.f,0.f,0.f,0.f);
        float4 accZ = make_float4(0.f,0.f,0.f,0.f);
        float4 accN = make_float4(0.f,0.f,0.f,0.f);

        // pass 1: A = h_hi, B = W_hi then W_lo (registers)
#pragma unroll
        for (int kt = 0; kt < 16; kt++){
            unsigned af[4];
            ldsm_x4_(af, abase + kt*32);
            mma_bf16_(accR, af, Bf[kt][0][0]);
            mma_bf16_(accZ, af, Bf[kt][1][0]);
            mma_bf16_(accN, af, Bf[kt][2][0]);
            mma_bf16_(accR, af, Bf[kt][0][1]);
            mma_bf16_(accZ, af, Bf[kt][1][1]);
            mma_bf16_(accN, af, Bf[kt][2][1]);
        }

        // gi loads issue here; latency hidden under pass 2
        float2 grA, gzA, gnA, grB, gzB, gnB;
        {
            const float* pA = gi + ((size_t)bbA*steps + pos)*G3 + jglob0;
            const float* pB = gi + ((size_t)bbB*steps + pos)*G3 + jglob0;
            grA = *(const float2*)(pA); gzA = *(const float2*)(pA+256); gnA = *(const float2*)(pA+512);
            grB = *(const float2*)(pB); gzB = *(const float2*)(pB+256); gnB = *(const float2*)(pB+512);
        }

        // pass 2: A = h_lo (k+512B), B = W_hi
#pragma unroll
        for (int kt = 0; kt < 16; kt++){
            unsigned af[4];
            ldsm_x4_(af, abase + 512 + kt*32);
            mma_bf16_(accR, af, Bf[kt][0][0]);
            mma_bf16_(accZ, af, Bf[kt][1][0]);
            mma_bf16_(accN, af, Bf[kt][2][0]);
        }

        float2 br2 = *(const float2*)(bhh       + jglob0);
        float2 bz2 = *(const float2*)(bhh + 256 + jglob0);
        float2 bn2 = *(const float2*)(bhh + 512 + jglob0);

        float rA0 = fsig_(grA.x + accR.x + br2.x);
        float zA0 = fsig_(gzA.x + accZ.x + bz2.x);
        float nA0 = ftanh_(gnA.x + rA0*(accN.x + bn2.x));
        float hA0 = (1.f - zA0)*nA0 + zA0*hpA0; hpA0 = hA0;
        float rA1 = fsig_(grA.y + accR.y + br2.y);
        float zA1 = fsig_(gzA.y + accZ.y + bz2.y);
        float nA1 = ftanh_(gnA.y + rA1*(accN.y + bn2.y));
        float hA1 = (1.f - zA1)*nA1 + zA1*hpA1; hpA1 = hA1;
        float rB0 = fsig_(grB.x + accR.z + br2.x);
        float zB0 = fsig_(gzB.x + accZ.z + bz2.x);
        float nB0 = ftanh_(gnB.x + rB0*(accN.z + bn2.x));
        float hB0 = (1.f - zB0)*nB0 + zB0*hpB0; hpB0 = hB0;
        float rB1 = fsig_(grB.y + accR.w + br2.y);
        float zB1 = fsig_(gzB.y + accZ.w + bz2.y);
        float nB1 = ftanh_(gnB.y + rB1*(accN.w + bn2.y));
        float hB1 = (1.f - zB1)*nB1 + zB1*hpB1; hpB1 = hB1;

        bf16 hiA0, loA0, hiA1, loA1, hiB0, loB0, hiB1, loB1;
        split_bf16_(hA0, hiA0, loA0); split_bf16_(hA1, hiA1, loA1);
        split_bf16_(hB0, hiB0, loB0); split_bf16_(hB1, hiB1, loB1);
        unsigned uAhi = pack_bf2_(hiA0, hiA1), uAlo = pack_bf2_(loA0, loA1);
        unsigned uBhi = pack_bf2_(hiB0, hiB1), uBlo = pack_bf2_(loB0, loB1);

        // write NEXT buffer on all 4 CTAs
        {
            unsigned offAhi = (unsigned)((r*GRU_HST + jglob0)*2);
            unsigned offAlo = offAhi + 512;
            unsigned offBhi = (unsigned)(((r+8)*GRU_HST + jglob0)*2);
            unsigned offBlo = offBhi + 512;
            unsigned p0 = mapa_(wb, 0), p1 = mapa_(wb, 1), p2 = mapa_(wb, 2), p3 = mapa_(wb, 3);
            st_cluster_u32_(p0 + offAhi, uAhi); st_cluster_u32_(p0 + offAlo, uAlo);
            st_cluster_u32_(p0 + offBhi, uBhi); st_cluster_u32_(p0 + offBlo, uBlo);
            st_cluster_u32_(p1 + offAhi, uAhi); st_cluster_u32_(p1 + offAlo, uAlo);
            st_cluster_u32_(p1 + offBhi, uBhi); st_cluster_u32_(p1 + offBlo, uBlo);
            st_cluster_u32_(p2 + offAhi, uAhi); st_cluster_u32_(p2 + offAlo, uAlo);
            st_cluster_u32_(p2 + offBhi, uBhi); st_cluster_u32_(p2 + offBlo, uBlo);
            st_cluster_u32_(p3 + offAhi, uAhi); st_cluster_u32_(p3 + offAlo, uAlo);
            st_cluster_u32_(p3 + offBhi, uBhi); st_cluster_u32_(p3 + offBlo, uBlo);
        }
        cluster_arrive_();

        // global outputs overlap the barrier
        if (chain == 2){
            if (step == steps - 1){
                *(float2*)(outp + (size_t)bbA*H_ + jglob0) = make_float2(hA0, hA1);
                *(float2*)(outp + (size_t)bbB*H_ + jglob0) = make_float2(hB0, hB1);
            }
        } else {
            *(float2*)(outp + ((size_t)bbA*S_ + pos)*H_ + jglob0) = make_float2(hA0, hA1);
            *(float2*)(outp + ((size_t)bbB*S_ + pos)*H_ + jglob0) = make_float2(hB0, hB1);
        }
        cluster_wait_();
    }
}

// ---------------- 4) attention + read + tanh(q*read) -> split-bf16 A' ----------------
__global__ __launch_bounds__(256) void attn_kernel(){
    int b = blockIdx.x, tid = threadIdx.x;
    int lane = tid & 31, w = tid >> 5;
    __shared__ float en[S_ + 6];
    const float* pq = g_q + (size_t)b*H_;

    // phase 1: warps compute energies in parallel over s
    for (int s = w; s < S_; s += 8){
        const float* pf = g_outf + ((size_t)b*S_ + s)*H_;
        const float* pb = g_outb + ((size_t)b*S_ + s)*H_;
        float p = 0.f;
#pragma unroll
        for (int c = 0; c < 8; c++){
            int hh = c*32 + lane;
            p += (pf[hh] + pb[hh]) * pq[hh];
        }
#pragma unroll
        for (int o = 16; o; o >>= 1) p += __shfl_xor_sync(0xffffffffu, p, o);
        if (lane == 0) en[s] = p;
    }
    __syncthreads();

    // phase 2: softmax + weighted read per h
    int h = tid;
    float qh = pq[h];
    float mx = -1e30f;
    for (int s = 0; s < S_; s++) mx = fmaxf(mx, en[s]);
    float sum = 0.f;
    for (int s = 0; s < S_; s++) sum += fexp_(en[s] - mx);
    float inv = frcp_(sum);
    float rd = 0.f;
    for (int s = 0; s < S_; s++){
        float a = fexp_(en[s] - mx) * inv;
        rd += a * (g_outf[((size_t)b*S_ + s)*H_ + h] + g_outb[((size_t)b*S_ + s)*H_ + h]);
    }
    float v = ftanh_(qh * rd);
    bf16 hi, lo; split_bf16_(v, hi, lo);
    bf16* dst = g_afA + (size_t)b*KTOT;
    dst[h] = hi; dst[h + 256] = hi; dst[h + 512] = lo;
}

// ---------------- launch ----------------
extern "C" void kernel_launch(void* const* d_in, const int* in_sizes, int n_in,
                              void* d_out, int out_size)
{
    const int*   contexts  = (const int*)  d_in[0];
    const int*   questions = (const int*)  d_in[1];
    const float* emb       = (const float*)d_in[2];
    const float* Wih_f     = (const float*)d_in[3];
    const float* Whh_f     = (const float*)d_in[4];
    const float* bih_f     = (const float*)d_in[5];
    const float* bhh_f     = (const float*)d_in[6];
    const float* Wih_b     = (const float*)d_in[7];
    const float* Whh_b     = (const float*)d_in[8];
    const float* bih_b     = (const float*)d_in[9];
    const float* bhh_b     = (const float*)d_in[10];
    const float* Wih_q     = (const float*)d_in[11];
    const float* Whh_q     = (const float*)d_in[12];
    const float* bih_q     = (const float*)d_in[13];
    const float* bhh_q     = (const float*)d_in[14];
    const float* Wo        = (const float*)d_in[15];
    const float* bo        = (const float*)d_in[16];
    float* out = (float*)d_out;

    cudaFuncSetAttribute(gru_kernel, cudaFuncAttributeMaxDynamicSharedMemorySize, GRU_SMEM_BYTES);

    // 1) fused prep: embeddings + all weight splits in ONE launch
    prep_kernel<<<PREP_TOTAL, 256>>>(contexts, questions, emb, Wih_f, Wih_b, Wih_q, Wo);

    // 2) input-gate GEMMs on tensor cores
    bgemm3_kernel<<<dim3(B_*S_/128, G3/64, 3), 256>>>(bih_f, bih_b, bih_q);

    // 3) GRU chains on tensor cores (24 clusters x 4 CTAs)
    gru_kernel<<<96, 256, GRU_SMEM_BYTES>>>(Whh_f, Whh_b, Whh_q, bhh_f, bhh_b, bhh_q);

    // 4) attention + read + tanh (fused split-bf16 write)
    attn_kernel<<<B_, 256>>>();

    // 5) vocab projection on tensor cores
    bgemm_vocab_kernel<<<dim3(1, VPAD/64), 256>>>(bo, out);
}

// round 11
// speedup vs baseline: 4.0650x; 1.0482x over previous
#include <cuda_runtime.h>
#include <cuda_bf16.h>
#include <cstdint>
#include <cstdio>

#define B_  128
#define S_  50
#define T_  32
#define TQ_ 32
#define H_  256
#define V_  50257
#define G3  768
#define KTOT 768
#define VPAD 50304

typedef unsigned long long ull;
typedef __nv_bfloat16 bf16;

// ---------------- scratch (device globals; no allocation) ----------------
__device__ bf16  g_ctxA[B_*S_*KTOT];
__device__ bf16  g_qA  [B_*TQ_*KTOT];
__device__ bf16  g_afA [B_*KTOT];
__device__ bf16  g_wfA [G3*KTOT];
__device__ bf16  g_wbA [G3*KTOT];
__device__ bf16  g_wqA [G3*KTOT];
__device__ float g_gif [B_*S_*G3];
__device__ float g_gib [B_*S_*G3];
__device__ float g_giq [B_*TQ_*G3];
__device__ float g_outf[B_*S_*H_];
__device__ float g_outb[B_*S_*H_];
__device__ float g_q   [B_*H_];

// ---------------- helpers ----------------
__device__ __forceinline__ float fexp_(float x){
    float y;
    asm("ex2.approx.ftz.f32 %0, %1;" : "=f"(y) : "f"(x * 1.4426950408889634f));
    return y;
}
__device__ __forceinline__ float frcp_(float x){
    float y; asm("rcp.approx.ftz.f32 %0, %1;" : "=f"(y) : "f"(x)); return y;
}
__device__ __forceinline__ float fsig_(float x){ return frcp_(1.f + fexp_(-x)); }
__device__ __forceinline__ float ftanh_(float x){ return 2.f*frcp_(1.f + fexp_(-2.f*x)) - 1.f; }

__device__ __forceinline__ void split_bf16_(float v, bf16& hi, bf16& lo){
    hi = __float2bfloat16(v);
    lo = __float2bfloat16(v - __bfloat162float(hi));
}
__device__ __forceinline__ unsigned pack_bf2_(bf16 a, bf16 b){
    unsigned short x = *reinterpret_cast<unsigned short*>(&a);
    unsigned short y = *reinterpret_cast<unsigned short*>(&b);
    return (unsigned)x | ((unsigned)y << 16);
}
__device__ __forceinline__ unsigned smem_u32_(const void* p){
    unsigned r;
    asm("{ .reg .u64 t; cvta.to.shared.u64 t, %1; cvt.u32.u64 %0, t; }" : "=r"(r) : "l"(p));
    return r;
}
__device__ __forceinline__ unsigned mapa_(unsigned laddr, unsigned rank){
    unsigned r;
    asm("mapa.shared::cluster.u32 %0, %1, %2;" : "=r"(r) : "r"(laddr), "r"(rank));
    return r;
}
__device__ __forceinline__ void st_cluster_u32_(unsigned addr, unsigned v){
    asm volatile("st.shared::cluster.u32 [%0], %1;" :: "r"(addr), "r"(v) : "memory");
}
__device__ __forceinline__ void cluster_arrive_(){
    asm volatile("barrier.cluster.arrive.aligned;" ::: "memory");
}
__device__ __forceinline__ void cluster_wait_(){
    asm volatile("barrier.cluster.wait.aligned;" ::: "memory");
}
__device__ __forceinline__ unsigned ctarank_(){
    unsigned r; asm("mov.u32 %0, %%cluster_ctarank;" : "=r"(r)); return r;
}
__device__ __forceinline__ void mbar_init_(unsigned addr, unsigned cnt){
    asm volatile("mbarrier.init.shared.b64 [%0], %1;" :: "r"(addr), "r"(cnt) : "memory");
}
__device__ __forceinline__ void mbar_arrive_cluster_(unsigned remote_addr){
    asm volatile("mbarrier.arrive.shared::cluster.b64 _, [%0];" :: "r"(remote_addr) : "memory");
}
__device__ __forceinline__ void mbar_wait_parity_(unsigned addr, unsigned parity){
    asm volatile(
        "{\n\t"
        ".reg .pred P1;\n\t"
        "WAIT_LOOP_%=:\n\t"
        "mbarrier.try_wait.parity.shared::cta.b64 P1, [%0], %1, 0x989680;\n\t"
        "@P1 bra.uni WAIT_DONE_%=;\n\t"
        "bra.uni WAIT_LOOP_%=;\n\t"
        "WAIT_DONE_%=:\n\t"
        "}"
        :: "r"(addr), "r"(parity) : "memory");
}
__device__ __forceinline__ void fence_cluster_(){
    asm volatile("fence.acq_rel.cluster;" ::: "memory");
}
__device__ __forceinline__ void mma_bf16_(float4& d, const unsigned a[4], const unsigned b[2]){
    asm("mma.sync.aligned.m16n8k16.row.col.f32.bf16.bf16.f32 "
        "{%0,%1,%2,%3}, {%4,%5,%6,%7}, {%8,%9}, {%0,%1,%2,%3};"
        : "+f"(d.x), "+f"(d.y), "+f"(d.z), "+f"(d.w)
        : "r"(a[0]), "r"(a[1]), "r"(a[2]), "r"(a[3]), "r"(b[0]), "r"(b[1]));
}
__device__ __forceinline__ void ldsm_x4_(unsigned af[4], unsigned addr){
    asm volatile("ldmatrix.sync.aligned.m8n8.x4.shared.b16 {%0,%1,%2,%3}, [%4];"
        : "=r"(af[0]), "=r"(af[1]), "=r"(af[2]), "=r"(af[3]) : "r"(addr));
}

// ---------------- 1) fused prep: embed_pe | qemb | convW3 (no convWo anymore) -----
#define PREP_EMB   (B_*S_)                 // 6400
#define PREP_QEMB  (PREP_EMB + B_*TQ_)     // +4096
#define PREP_TOTAL (PREP_QEMB + 3*G3)      // +2304 = 12800

__global__ __launch_bounds__(256) void prep_kernel(
    const int* __restrict__ ctx, const int* __restrict__ q, const float* __restrict__ emb,
    const float* __restrict__ Wf, const float* __restrict__ Wb, const float* __restrict__ Wq)
{
    int bid = blockIdx.x;
    int h   = threadIdx.x;
    if (bid < PREP_EMB){
        int bs = bid;
        __shared__ int ids[T_];
        if (h < T_) ids[h] = ctx[bs*T_ + h];
        __syncthreads();
        float e = (float)h * (1.0f/255.0f);
        float acc = 0.f;
#pragma unroll
        for (int t = 0; t < T_; t++){
            float s = (float)t * (1.0f/31.0f);
            float l = 1.0f - s - e*(1.0f - 2.0f*s);
            acc += emb[(size_t)ids[t]*H_ + h] * l;
        }
        bf16 hi, lo; split_bf16_(acc, hi, lo);
        bf16* dst = g_ctxA + (size_t)bs*KTOT;
        dst[h] = hi; dst[h + 256] = hi; dst[h + 512] = lo;
    } else if (bid < PREP_QEMB){
        int i = bid - PREP_EMB;
        float v = emb[(size_t)q[i]*H_ + h];
        bf16 hi, lo; split_bf16_(v, hi, lo);
        bf16* dst = g_qA + (size_t)i*KTOT;
        dst[h] = hi; dst[h + 256] = hi; dst[h + 512] = lo;
    } else {
        int idx = bid - PREP_QEMB;
        int sel = idx / G3, n = idx % G3;
        const float* W; bf16* D;
        if (sel == 0){ W = Wf; D = g_wfA; }
        else if (sel == 1){ W = Wb; D = g_wbA; }
        else { W = Wq; D = g_wqA; }
        float v = W[(size_t)n*256 + h];
        bf16 hi, lo; split_bf16_(v, hi, lo);
        bf16* dst = D + (size_t)n*KTOT;
        dst[h] = hi; dst[h + 256] = lo; dst[h + 512] = hi;
    }
}

// ---------------- 2) split-bf16 tensor GEMM for gi (K=768 pre-split weights) ------
#define AST 72
__device__ __forceinline__ void bgemm_body(const bf16* __restrict__ A,
                                           const bf16* __restrict__ W,
                                           const float* __restrict__ bias,
                                           float* __restrict__ C,
                                           int Nv, int bm, int bn)
{
    __shared__ bf16 As[128*AST];
    __shared__ bf16 Bs[64*AST];
    int tid = threadIdx.x;
    int lane = tid & 31, wid = tid >> 5;
    int wm = (wid & 3) * 32;
    int wn = (wid >> 2) * 32;

    float4 acc[2][4];
#pragma unroll
    for (int i = 0; i < 2; i++)
#pragma unroll
        for (int j = 0; j < 4; j++) acc[i][j] = make_float4(0.f,0.f,0.f,0.f);

    for (int k0 = 0; k0 < KTOT; k0 += 64){
#pragma unroll
        for (int i = 0; i < 4; i++){
            int idx = tid + i*256;
            int r = idx >> 3, ck = idx & 7;
            uint4 v = *(const uint4*)(A + (size_t)(bm + r)*KTOT + k0 + ck*8);
            *(uint4*)(As + r*AST + ck*8) = v;
        }
#pragma unroll
        for (int i = 0; i < 2; i++){
            int idx = tid + i*256;
            int r = idx >> 3, ck = idx & 7;
            uint4 v = *(const uint4*)(W + (size_t)(bn + r)*KTOT + k0 + ck*8);
            *(uint4*)(Bs + r*AST + ck*8) = v;
        }
        __syncthreads();
        int r = lane >> 2, c2 = (lane & 3) * 2;
#pragma unroll
        for (int kk = 0; kk < 4; kk++){
            unsigned af[2][4], bfr[4][2];
#pragma unroll
            for (int i = 0; i < 2; i++){
                const bf16* ab = As + (wm + i*16)*AST + kk*16;
                af[i][0] = *(const unsigned*)(ab + (r    )*AST + c2    );
                af[i][1] = *(const unsigned*)(ab + (r + 8)*AST + c2    );
                af[i][2] = *(const unsigned*)(ab + (r    )*AST + c2 + 8);
                af[i][3] = *(const unsigned*)(ab + (r + 8)*AST + c2 + 8);
            }
#pragma unroll
            for (int j = 0; j < 4; j++){
                const bf16* bb = Bs + (wn + j*8)*AST + kk*16;
                bfr[j][0] = *(const unsigned*)(bb + r*AST + c2    );
                bfr[j][1] = *(const unsigned*)(bb + r*AST + c2 + 8);
            }
#pragma unroll
            for (int i = 0; i < 2; i++)
#pragma unroll
                for (int j = 0; j < 4; j++)
                    mma_bf16_(acc[i][j], af[i], bfr[j]);
        }
        __syncthreads();
    }
    int r = lane >> 2, c2 = (lane & 3) * 2;
#pragma unroll
    for (int i = 0; i < 2; i++){
        int m0 = bm + wm + i*16 + r;
#pragma unroll
        for (int j = 0; j < 4; j++){
            int n0 = bn + wn + j*8 + c2;
            float4 a = acc[i][j];
            float b0 = bias[n0], b1 = bias[n0+1];
            *(float2*)(C + (size_t)m0*Nv + n0)     = make_float2(a.x + b0, a.y + b1);
            *(float2*)(C + (size_t)(m0+8)*Nv + n0) = make_float2(a.z + b0, a.w + b1);
        }
    }
}

__global__ __launch_bounds__(256) void bgemm3_kernel(
    const float* bias_f, const float* bias_b, const float* bias_q)
{
    const bf16 *A, *W; const float* bias; float* C; int M;
    if (blockIdx.z == 0){ A = g_ctxA; W = g_wfA; bias = bias_f; C = g_gif; M = B_*S_; }
    else if (blockIdx.z == 1){ A = g_ctxA; W = g_wbA; bias = bias_b; C = g_gib; M = B_*S_; }
    else { A = g_qA; W = g_wqA; bias = bias_q; C = g_giq; M = B_*TQ_; }
    int bm = blockIdx.x * 128;
    if (bm >= M) return;
    bgemm_body(A, W, bias, C, G3, bm, blockIdx.y * 64);
}

// ---------------- 2b) vocab GEMM: inline fp32 W split (no g_woA) ----------------
// C[m,n] = af[m,:] . Wo[n,:] + bo[n]; m=128, n-tile 64, K=256 fp32 -> 3-term split.
#define VOC_SMEM_BF16 (2*128*AST + 2*64*AST)
#define VOC_SMEM_BYTES (VOC_SMEM_BF16*2)
__global__ __launch_bounds__(256) void bgemm_vocab_kernel(
    const float* __restrict__ Wo, const float* __restrict__ bo, float* __restrict__ out)
{
    extern __shared__ bf16 vs[];
    bf16* Ah = vs;                 // [128][72]
    bf16* Al = vs + 128*AST;       // [128][72]
    bf16* Bh = vs + 2*128*AST;     // [64][72]
    bf16* Bl = Bh + 64*AST;        // [64][72]
    int tid = threadIdx.x;
    int lane = tid & 31, wid = tid >> 5;
    int wm = (wid & 3) * 32;
    int wn = (wid >> 2) * 32;
    int bn = blockIdx.y * 64;

    float4 acc[2][4];
#pragma unroll
    for (int i = 0; i < 2; i++)
#pragma unroll
        for (int j = 0; j < 4; j++) acc[i][j] = make_float4(0.f,0.f,0.f,0.f);

    for (int k0 = 0; k0 < 256; k0 += 64){
        // A planes from g_afA: hi at [k0..], lo at [512+k0..]
#pragma unroll
        for (int i = 0; i < 4; i++){
            int idx = tid + i*256;
            int r = idx >> 3, ck = idx & 7;
            *(uint4*)(Ah + r*AST + ck*8) = *(const uint4*)(g_afA + (size_t)r*KTOT + k0 + ck*8);
            *(uint4*)(Al + r*AST + ck*8) = *(const uint4*)(g_afA + (size_t)r*KTOT + 512 + k0 + ck*8);
        }
        // W fp32 tile [64 n][64 k] -> split into Bh/Bl
#pragma unroll
        for (int i = 0; i < 4; i++){
            int idx = tid + i*256;          // 1024 float4 chunks
            int r = idx >> 4, ck = idx & 15;
            int n = bn + r;
            float4 v = make_float4(0.f,0.f,0.f,0.f);
            if (n < V_) v = *(const float4*)(Wo + (size_t)n*256 + k0 + ck*4);
            bf16 h0,l0,h1,l1,h2,l2,h3,l3;
            split_bf16_(v.x,h0,l0); split_bf16_(v.y,h1,l1);
            split_bf16_(v.z,h2,l2); split_bf16_(v.w,h3,l3);
            *(uint2*)(Bh + r*AST + ck*4) = make_uint2(pack_bf2_(h0,h1), pack_bf2_(h2,h3));
            *(uint2*)(Bl + r*AST + ck*4) = make_uint2(pack_bf2_(l0,l1), pack_bf2_(l2,l3));
        }
        __syncthreads();
        int r = lane >> 2, c2 = (lane & 3) * 2;
#pragma unroll
        for (int kk = 0; kk < 4; kk++){
            unsigned ah[2][4], al[2][4], bh[4][2], bl[4][2];
#pragma unroll
            for (int i = 0; i < 2; i++){
                const bf16* ab = Ah + (wm + i*16)*AST + kk*16;
                const bf16* al_ = Al + (wm + i*16)*AST + kk*16;
                ah[i][0] = *(const unsigned*)(ab  + (r    )*AST + c2    );
                ah[i][1] = *(const unsigned*)(ab  + (r + 8)*AST + c2    );
                ah[i][2] = *(const unsigned*)(ab  + (r    )*AST + c2 + 8);
                ah[i][3] = *(const unsigned*)(ab  + (r + 8)*AST + c2 + 8);
                al[i][0] = *(const unsigned*)(al_ + (r    )*AST + c2    );
                al[i][1] = *(const unsigned*)(al_ + (r + 8)*AST + c2    );
                al[i][2] = *(const unsigned*)(al_ + (r    )*AST + c2 + 8);
                al[i][3] = *(const unsigned*)(al_ + (r + 8)*AST + c2 + 8);
            }
#pragma unroll
            for (int j = 0; j < 4; j++){
                const bf16* bbh = Bh + (wn + j*8)*AST + kk*16;
                const bf16* bbl = Bl + (wn + j*8)*AST + kk*16;
                bh[j][0] = *(const unsigned*)(bbh + r*AST + c2    );
                bh[j][1] = *(const unsigned*)(bbh + r*AST + c2 + 8);
                bl[j][0] = *(const unsigned*)(bbl + r*AST + c2    );
                bl[j][1] = *(const unsigned*)(bbl + r*AST + c2 + 8);
            }
#pragma unroll
            for (int i = 0; i < 2; i++)
#pragma unroll
                for (int j = 0; j < 4; j++){
                    mma_bf16_(acc[i][j], ah[i], bh[j]);
                    mma_bf16_(acc[i][j], ah[i], bl[j]);
                    mma_bf16_(acc[i][j], al[i], bh[j]);
                }
        }
        __syncthreads();
    }
    // epilogue: Nv = V_ (odd stride) -> scalar stores
    int r = lane >> 2, c2 = (lane & 3) * 2;
#pragma unroll
    for (int i = 0; i < 2; i++){
        int m0 = wm + i*16 + r;
#pragma unroll
        for (int j = 0; j < 4; j++){
            int n0 = bn + wn + j*8 + c2;
            if (n0 < V_){
                float4 a = acc[i][j];
                float b0 = bo[n0];
                out[(size_t)m0*V_ + n0]     = a.x + b0;
                out[(size_t)(m0+8)*V_ + n0] = a.z + b0;
                if (n0 + 1 < V_){
                    float b1 = bo[n0+1];
                    out[(size_t)m0*V_ + n0 + 1]     = a.y + b1;
                    out[(size_t)(m0+8)*V_ + n0 + 1] = a.w + b1;
                }
            }
        }
    }
}

// ---------------- 3) GRU on tensor cores: mbarrier cluster sync ----------------
#define GRU_WST 264
#define GRU_HST 520
#define GRU_WPLANE (192*GRU_WST)
#define GRU_SMEM_BF16 (2*GRU_WPLANE + 16*GRU_HST)
#define GRU_SMEM_BYTES (GRU_SMEM_BF16*2)

__global__ void __cluster_dims__(4,1,1) __launch_bounds__(256,1)
gru_kernel(const float* __restrict__ Whh_f, const float* __restrict__ Whh_b, const float* __restrict__ Whh_q,
           const float* __restrict__ bhh_f, const float* __restrict__ bhh_b, const float* __restrict__ bhh_q)
{
    extern __shared__ bf16 smb[];
    __shared__ ull gru_mbar;              // static smem mbarrier (never aliased)
    bf16* Whi   = smb;                    // [192][264] (dead after preload)
    bf16* Wlo   = smb + GRU_WPLANE;       // [192][264]
    bf16* hbuf0 = smb + 2*GRU_WPLANE;     // [16][520]: k 0-255 hi, 256-511 lo
    bf16* hbuf1 = smb;                    // aliases Whi region

    int tid  = threadIdx.x;
    int lane = tid & 31, w = tid >> 5;
    unsigned rank = ctarank_();
    int cid   = blockIdx.x >> 2;
    int chain = cid >> 3;
    int b0    = (cid & 7) * 16;

    const float *Whh, *bhh, *gi;
    float* outp;
    int steps;
    if (chain == 0){ Whh = Whh_f; bhh = bhh_f; gi = g_gif; outp = g_outf; steps = S_;  }
    else if (chain == 1){ Whh = Whh_b; bhh = bhh_b; gi = g_gib; outp = g_outb; steps = S_;  }
    else { Whh = Whh_q; bhh = bhh_q; gi = g_giq; outp = g_q;    steps = TQ_; }

    unsigned mbar_addr = smem_u32_(&gru_mbar);
    if (tid == 0) mbar_init_(mbar_addr, 1024u);

    // ---- stage + split Whh slice into smem; zero hbuf0
    {
#pragma unroll 4
        for (int rr = 0; rr < 192; rr++){
            int grow = (rr >> 6)*256 + (int)rank*64 + (rr & 63);
            float v = Whh[(size_t)grow*256 + tid];
            bf16 hi, lo; split_bf16_(v, hi, lo);
            Whi[rr*GRU_WST + tid] = hi;
            Wlo[rr*GRU_WST + tid] = lo;
        }
        unsigned* hz = (unsigned*)hbuf0;
        for (int i = tid; i < 16*GRU_HST/2; i += 256) hz[i] = 0u;
    }
    __syncthreads();

    // ---- fragment geometry
    int r  = lane >> 2;
    int c2 = (lane & 3) * 2;
    int jglob0 = (int)rank*64 + w*8 + c2;

    // ---- preload W fragments to registers: Bf[kt][gate][plane][reg]
    unsigned Bf[16][3][2][2];
#pragma unroll
    for (int kt = 0; kt < 16; kt++){
#pragma unroll
        for (int g = 0; g < 3; g++){
            const bf16* ph = Whi + (g*64 + w*8 + r)*GRU_WST + kt*16 + c2;
            const bf16* pl = Wlo + (g*64 + w*8 + r)*GRU_WST + kt*16 + c2;
            Bf[kt][g][0][0] = *(const unsigned*)(ph);
            Bf[kt][g][0][1] = *(const unsigned*)(ph + 8);
            Bf[kt][g][1][0] = *(const unsigned*)(pl);
            Bf[kt][g][1][1] = *(const unsigned*)(pl + 8);
        }
    }

    unsigned hb0 = smem_u32_(hbuf0), hb1 = smem_u32_(hbuf1);
    unsigned arow = (unsigned)((lane & 15)*GRU_HST*2 + ((lane >> 4) << 3)*2);

    // peer mbarrier addresses (fixed; hoisted)
    unsigned mb0 = mapa_(mbar_addr, 0), mb1 = mapa_(mbar_addr, 1);
    unsigned mb2 = mapa_(mbar_addr, 2), mb3 = mapa_(mbar_addr, 3);

    int bbA = b0 + r, bbB = b0 + r + 8;
    float hpA0 = 0.f, hpA1 = 0.f, hpB0 = 0.f, hpB1 = 0.f;

    // staging + preloads + mbarrier init visible cluster-wide before step 0
    cluster_arrive_();
    cluster_wait_();

    for (int step = 0; step < steps; step++){
        int pos = (chain == 1) ? (S_ - 1 - step) : step;
        unsigned rb = (step & 1) ? hb1 : hb0;
        unsigned wb = (step & 1) ? hb0 : hb1;
        unsigned abase = rb + arow;
        bool last = (step == steps - 1);

        float4 accR = make_float4(0.f,0.f,0.f,0.f);
        float4 accZ = make_float4(0.f,0.f,0.f,0.f);
        float4 accN = make_float4(0.f,0.f,0.f,0.f);

        // pass 1: A = h_hi, B = W_hi then W_lo (registers)
#pragma unroll
        for (int kt = 0; kt < 16; kt++){
            unsigned af[4];
            ldsm_x4_(af, abase + kt*32);
            mma_bf16_(accR, af, Bf[kt][0][0]);
            mma_bf16_(accZ, af, Bf[kt][1][0]);
            mma_bf16_(accN, af, Bf[kt][2][0]);
            mma_bf16_(accR, af, Bf[kt][0][1]);
            mma_bf16_(accZ, af, Bf[kt][1][1]);
            mma_bf16_(accN, af, Bf[kt][2][1]);
        }

        // gi loads issue here; latency hidden under pass 2
        float2 grA, gzA, gnA, grB, gzB, gnB;
        {
            const float* pA = gi + ((size_t)bbA*steps + pos)*G3 + jglob0;
            const float* pB = gi + ((size_t)bbB*steps + pos)*G3 + jglob0;
            grA = *(const float2*)(pA); gzA = *(const float2*)(pA+256); gnA = *(const float2*)(pA+512);
            grB = *(const float2*)(pB); gzB = *(const float2*)(pB+256); gnB = *(const float2*)(pB+512);
        }

        // pass 2: A = h_lo (k+512B), B = W_hi
#pragma unroll
        for (int kt = 0; kt < 16; kt++){
            unsigned af[4];
            ldsm_x4_(af, abase + 512 + kt*32);
            mma_bf16_(accR, af, Bf[kt][0][0]);
            mma_bf16_(accZ, af, Bf[kt][1][0]);
            mma_bf16_(accN, af, Bf[kt][2][0]);
        }

        float2 br2 = *(const float2*)(bhh       + jglob0);
        float2 bz2 = *(const float2*)(bhh + 256 + jglob0);
        float2 bn2 = *(const float2*)(bhh + 512 + jglob0);

        float rA0 = fsig_(grA.x + accR.x + br2.x);
        float zA0 = fsig_(gzA.x + accZ.x + bz2.x);
        float nA0 = ftanh_(gnA.x + rA0*(accN.x + bn2.x));
        float hA0 = (1.f - zA0)*nA0 + zA0*hpA0; hpA0 = hA0;
        float rA1 = fsig_(grA.y + accR.y + br2.y);
        float zA1 = fsig_(gzA.y + accZ.y + bz2.y);
        float nA1 = ftanh_(gnA.y + rA1*(accN.y + bn2.y));
        float hA1 = (1.f - zA1)*nA1 + zA1*hpA1; hpA1 = hA1;
        float rB0 = fsig_(grB.x + accR.z + br2.x);
        float zB0 = fsig_(gzB.x + accZ.z + bz2.x);
        float nB0 = ftanh_(gnB.x + rB0*(accN.z + bn2.x));
        float hB0 = (1.f - zB0)*nB0 + zB0*hpB0; hpB0 = hB0;
        float rB1 = fsig_(grB.y + accR.w + br2.y);
        float zB1 = fsig_(gzB.y + accZ.w + bz2.y);
        float nB1 = ftanh_(gnB.y + rB1*(accN.w + bn2.y));
        float hB1 = (1.f - zB1)*nB1 + zB1*hpB1; hpB1 = hB1;

        if (!last){
            bf16 hiA0, loA0, hiA1, loA1, hiB0, loB0, hiB1, loB1;
            split_bf16_(hA0, hiA0, loA0); split_bf16_(hA1, hiA1, loA1);
            split_bf16_(hB0, hiB0, loB0); split_bf16_(hB1, hiB1, loB1);
            unsigned uAhi = pack_bf2_(hiA0, hiA1), uAlo = pack_bf2_(loA0, loA1);
            unsigned uBhi = pack_bf2_(hiB0, hiB1), uBlo = pack_bf2_(loB0, loB1);

            unsigned offAhi = (unsigned)((r*GRU_HST + jglob0)*2);
            unsigned offAlo = offAhi + 512;
            unsigned offBhi = (unsigned)(((r+8)*GRU_HST + jglob0)*2);
            unsigned offBlo = offBhi + 512;
            unsigned p0 = mapa_(wb, 0), p1 = mapa_(wb, 1), p2 = mapa_(wb, 2), p3 = mapa_(wb, 3);
            st_cluster_u32_(p0 + offAhi, uAhi); st_cluster_u32_(p0 + offAlo, uAlo);
            st_cluster_u32_(p0 + offBhi, uBhi); st_cluster_u32_(p0 + offBlo, uBlo);
            st_cluster_u32_(p1 + offAhi, uAhi); st_cluster_u32_(p1 + offAlo, uAlo);
            st_cluster_u32_(p1 + offBhi, uBhi); st_cluster_u32_(p1 + offBlo, uBlo);
            st_cluster_u32_(p2 + offAhi, uAhi); st_cluster_u32_(p2 + offAlo, uAlo);
            st_cluster_u32_(p2 + offBhi, uBhi); st_cluster_u32_(p2 + offBlo, uBlo);
            st_cluster_u32_(p3 + offAhi, uAhi); st_cluster_u32_(p3 + offAlo, uAlo);
            st_cluster_u32_(p3 + offBhi, uBhi); st_cluster_u32_(p3 + offBlo, uBlo);

            // release: order DSMEM stores (and our smem reads) before arrivals
            fence_cluster_();
            mbar_arrive_cluster_(mb0);
            mbar_arrive_cluster_(mb1);
            mbar_arrive_cluster_(mb2);
            mbar_arrive_cluster_(mb3);
        }

        // global outputs overlap the arrive/wait window
        if (chain == 2){
            if (last){
                *(float2*)(outp + (size_t)bbA*H_ + jglob0) = make_float2(hA0, hA1);
                *(float2*)(outp + (size_t)bbB*H_ + jglob0) = make_float2(hB0, hB1);
            }
        } else {
            *(float2*)(outp + ((size_t)bbA*S_ + pos)*H_ + jglob0) = make_float2(hA0, hA1);
            *(float2*)(outp + ((size_t)bbB*S_ + pos)*H_ + jglob0) = make_float2(hB0, hB1);
        }

        if (!last){
            mbar_wait_parity_(mbar_addr, (unsigned)(step & 1));
            fence_cluster_();   // acquire: peer stores visible before next reads
        }
    }
}

// ---------------- 4) attention + read + tanh(q*read) -> split-bf16 A' ----------------
__global__ __launch_bounds__(256) void attn_kernel(){
    int b = blockIdx.x, tid = threadIdx.x;
    int lane = tid & 31, w = tid >> 5;
    __shared__ float en[S_];
    __shared__ float aw[S_];
    const float* pq = g_q + (size_t)b*H_;

    // phase 1: warps compute energies in parallel over s
    for (int s = w; s < S_; s += 8){
        const float* pf = g_outf + ((size_t)b*S_ + s)*H_;
        const float* pb = g_outb + ((size_t)b*S_ + s)*H_;
        float p = 0.f;
#pragma unroll
        for (int c = 0; c < 8; c++){
            int hh = c*32 + lane;
            p += (pf[hh] + pb[hh]) * pq[hh];
        }
#pragma unroll
        for (int o = 16; o; o >>= 1) p += __shfl_xor_sync(0xffffffffu, p, o);
        if (lane == 0) en[s] = p;
    }
    __syncthreads();

    // phase 2a: softmax weights once (threads < S_)
    if (tid < S_){
        float mx = -1e30f;
        for (int s = 0; s < S_; s++) mx = fmaxf(mx, en[s]);
        float sum = 0.f;
        for (int s = 0; s < S_; s++) sum += fexp_(en[s] - mx);
        aw[tid] = fexp_(en[tid] - mx) * frcp_(sum);
    }
    __syncthreads();

    // phase 2b: weighted read per h
    int h = tid;
    float qh = pq[h];
    float rd = 0.f;
#pragma unroll 2
    for (int s = 0; s < S_; s++){
        rd += aw[s] * (g_outf[((size_t)b*S_ + s)*H_ + h] + g_outb[((size_t)b*S_ + s)*H_ + h]);
    }
    float v = ftanh_(qh * rd);
    bf16 hi, lo; split_bf16_(v, hi, lo);
    bf16* dst = g_afA + (size_t)b*KTOT;
    dst[h] = hi; dst[h + 256] = hi; dst[h + 512] = lo;
}

// ---------------- launch ----------------
extern "C" void kernel_launch(void* const* d_in, const int* in_sizes, int n_in,
                              void* d_out, int out_size)
{
    const int*   contexts  = (const int*)  d_in[0];
    const int*   questions = (const int*)  d_in[1];
    const float* emb       = (const float*)d_in[2];
    const float* Wih_f     = (const float*)d_in[3];
    const float* Whh_f     = (const float*)d_in[4];
    const float* bih_f     = (const float*)d_in[5];
    const float* bhh_f     = (const float*)d_in[6];
    const float* Wih_b     = (const float*)d_in[7];
    const float* Whh_b     = (const float*)d_in[8];
    const float* bih_b     = (const float*)d_in[9];
    const float* bhh_b     = (const float*)d_in[10];
    const float* Wih_q     = (const float*)d_in[11];
    const float* Whh_q     = (const float*)d_in[12];
    const float* bih_q     = (const float*)d_in[13];
    const float* bhh_q     = (const float*)d_in[14];
    const float* Wo        = (const float*)d_in[15];
    const float* bo        = (const float*)d_in[16];
    float* out = (float*)d_out;

    cudaFuncSetAttribute(gru_kernel, cudaFuncAttributeMaxDynamicSharedMemorySize, GRU_SMEM_BYTES);
    cudaFuncSetAttribute(bgemm_vocab_kernel, cudaFuncAttributeMaxDynamicSharedMemorySize, VOC_SMEM_BYTES);

    // 1) fused prep: embeddings + gi weight splits in ONE launch (no Wo split)
    prep_kernel<<<PREP_TOTAL, 256>>>(contexts, questions, emb, Wih_f, Wih_b, Wih_q);

    // 2) input-gate GEMMs on tensor cores
    bgemm3_kernel<<<dim3(B_*S_/128, G3/64, 3), 256>>>(bih_f, bih_b, bih_q);

    // 3) GRU chains on tensor cores (24 clusters x 4 CTAs, mbarrier sync)
    gru_kernel<<<96, 256, GRU_SMEM_BYTES>>>(Whh_f, Whh_b, Whh_q, bhh_f, bhh_b, bhh_q);

    // 4) attention + read + tanh (fused split-bf16 write)
    attn_kernel<<<B_, 256>>>();

    // 5) vocab projection on tensor cores, inline fp32 W split
    bgemm_vocab_kernel<<<dim3(1, VPAD/64), 256, VOC_SMEM_BYTES>>>(Wo, bo, out);
}